// round 2
// baseline (speedup 1.0000x reference)
#include <cuda_runtime.h>

// Problem constants
#define BB 4
#define NN 4096
#define CC 512
#define HH 8
#define HD 64
#define MM 1024            // (64/2)^2 after spatial reduction
#define C3 1536

// ---- scratch (device globals; no allocations allowed) ----
__device__ float g_qkv[BB * NN * C3];     // [B,N,3C]
__device__ float g_xnorm[BB * MM * CC];   // conv+LN output [B,M,C]
__device__ float g_xr[BB * MM * HD];      // sr linear output [B,M,HD]
__device__ float g_kc[BB * HH * MM * HD]; // compressed K [B,H,M,HD]
__device__ float g_vc[BB * HH * MM * HD]; // compressed V [B,H,M,HD]
__device__ float g_attn[BB * NN * CC];    // attention out pre-proj [B,N,C]

// ============================================================
// Generic tiled SGEMM: C[M,N] = A[M,K] @ B[K,N] (+bias)
// BM=BN=64, BK=16, 256 threads, 4x4 per thread.
// M,N multiples of 64; K multiple of 16 (true for all calls here).
// ============================================================
__global__ void gemm64(const float* __restrict__ A, const float* __restrict__ B,
                       const float* __restrict__ bias, float* __restrict__ C,
                       int Md, int Nd, int Kd) {
    __shared__ float As[16][68];
    __shared__ float Bs[16][68];
    const int tx = threadIdx.x & 15;
    const int ty = threadIdx.x >> 4;
    const int rowBase = blockIdx.y * 64;
    const int colBase = blockIdx.x * 64;
    float acc[4][4] = {};

    for (int k0 = 0; k0 < Kd; k0 += 16) {
        #pragma unroll
        for (int t = threadIdx.x; t < 1024; t += 256) {
            int m = t >> 4, kk = t & 15;
            As[kk][m] = A[(long)(rowBase + m) * Kd + k0 + kk];
        }
        #pragma unroll
        for (int t = threadIdx.x; t < 1024; t += 256) {
            int kk = t >> 6, n = t & 63;
            Bs[kk][n] = B[(long)(k0 + kk) * Nd + colBase + n];
        }
        __syncthreads();
        #pragma unroll
        for (int kk = 0; kk < 16; kk++) {
            float a[4], b[4];
            #pragma unroll
            for (int i = 0; i < 4; i++) a[i] = As[kk][ty * 4 + i];
            #pragma unroll
            for (int j = 0; j < 4; j++) b[j] = Bs[kk][tx * 4 + j];
            #pragma unroll
            for (int i = 0; i < 4; i++)
                #pragma unroll
                for (int j = 0; j < 4; j++)
                    acc[i][j] += a[i] * b[j];
        }
        __syncthreads();
    }

    #pragma unroll
    for (int i = 0; i < 4; i++) {
        long r = rowBase + ty * 4 + i;
        #pragma unroll
        for (int j = 0; j < 4; j++) {
            int c = colBase + tx * 4 + j;
            float v = acc[i][j];
            if (bias) v += bias[c];
            C[r * Nd + c] = v;
        }
    }
}

// ============================================================
// Depthwise 2x2 stride-2 conv + bias + LayerNorm over C.
// One block per (b, m) output token; 128 threads, 4 channels each.
// Input x: [B, N=4096(=64x64 spatial), C]; output: [B, M=1024, C]
// ============================================================
__global__ void sr_conv_ln(const float* __restrict__ x, const float* __restrict__ wc,
                           const float* __restrict__ bc, const float* __restrict__ gam,
                           const float* __restrict__ bet, float* __restrict__ out) {
    const int bm = blockIdx.x;
    const int b = bm >> 10, m = bm & 1023;
    const int oi = m >> 5, oj = m & 31;
    // n00 = (2*oi)*64 + 2*oj
    const long base = ((long)b * NN + oi * 128 + oj * 2) * CC;
    __shared__ float red[4];
    const int tid = threadIdx.x; // 128 threads

    float y[4];
    float loc = 0.f;
    #pragma unroll
    for (int cc = 0; cc < 4; cc++) {
        int c = tid + cc * 128;
        float v = x[base + c]           * wc[c * 4 + 0]
                + x[base + CC + c]      * wc[c * 4 + 1]
                + x[base + 64 * CC + c] * wc[c * 4 + 2]
                + x[base + 65 * CC + c] * wc[c * 4 + 3]
                + bc[c];
        y[cc] = v;
        loc += v;
    }
    #pragma unroll
    for (int o = 16; o >= 1; o >>= 1) loc += __shfl_xor_sync(0xffffffffu, loc, o);
    if ((tid & 31) == 0) red[tid >> 5] = loc;
    __syncthreads();
    float mu = (red[0] + red[1] + red[2] + red[3]) * (1.f / 512.f);

    float lv = 0.f;
    #pragma unroll
    for (int cc = 0; cc < 4; cc++) { float d = y[cc] - mu; lv += d * d; }
    #pragma unroll
    for (int o = 16; o >= 1; o >>= 1) lv += __shfl_xor_sync(0xffffffffu, lv, o);
    __syncthreads();
    if ((tid & 31) == 0) red[tid >> 5] = lv;
    __syncthreads();
    float var = (red[0] + red[1] + red[2] + red[3]) * (1.f / 512.f);
    float inv = rsqrtf(var + 1e-5f);

    long ob = ((long)b * MM + m) * CC;
    #pragma unroll
    for (int cc = 0; cc < 4; cc++) {
        int c = tid + cc * 128;
        out[ob + c] = (y[cc] - mu) * inv * gam[c] + bet[c];
    }
}

// ============================================================
// Generic flash attention, HD=64, BM=BN=64, 256 threads.
// Per (b,h): O = softmax(scale * Q @ K^T) @ V with online softmax.
// Pointers addressed as base + b*bs + h*hs + row*rs (+ d).
// nq, nk must be multiples of 64 (they are: 1024/4096).
// ============================================================
#define FPAD 65
__global__ void flash64(
    const float* __restrict__ Qb, long qbs, long qhs, int qrs,
    const float* __restrict__ Kb, long kbs, long khs, int krs,
    const float* __restrict__ Vb, long vbs, long vhs, int vrs,
    float* __restrict__ Ob, long obs, long ohs, int ors,
    int nk, float scale) {
    extern __shared__ float smf[];
    float* Qs = smf;                 // [64][65]
    float* Ks = smf + 64 * FPAD;
    float* Vs = smf + 2 * 64 * FPAD;
    float* Ps = smf + 3 * 64 * FPAD;

    const int bh = blockIdx.y;
    const int b = bh >> 3, h = bh & 7;
    const float* Q = Qb + b * qbs + h * qhs + (long)blockIdx.x * 64 * qrs;
    const float* K = Kb + b * kbs + h * khs;
    const float* V = Vb + b * vbs + h * vhs;
    float*       O = Ob + b * obs + h * ohs + (long)blockIdx.x * 64 * ors;

    const int tx = threadIdx.x & 15;   // column group (keys for S, dims for O)
    const int ty = threadIdx.x >> 4;   // row group (queries)
    const int r0 = ty * 4;
    const int c0 = tx * 4;

    // load Q tile (scaled)
    for (int t = threadIdx.x; t < 4096; t += 256) {
        int r = t >> 6, d = t & 63;
        Qs[r * FPAD + d] = Q[(long)r * qrs + d] * scale;
    }

    float m_r[4], l_r[4], acc[4][4];
    #pragma unroll
    for (int i = 0; i < 4; i++) {
        m_r[i] = -1e30f; l_r[i] = 0.f;
        #pragma unroll
        for (int j = 0; j < 4; j++) acc[i][j] = 0.f;
    }

    for (int kt = 0; kt < nk; kt += 64) {
        __syncthreads();  // protect Qs (first iter) and Ks/Vs/Ps reuse
        for (int t = threadIdx.x; t < 4096; t += 256) {
            int r = t >> 6, d = t & 63;
            Ks[r * FPAD + d] = K[(long)(kt + r) * krs + d];
            Vs[r * FPAD + d] = V[(long)(kt + r) * vrs + d];
        }
        __syncthreads();

        // S = Qtile @ Ktile^T, 4x4 per thread
        float s[4][4];
        #pragma unroll
        for (int i = 0; i < 4; i++)
            #pragma unroll
            for (int j = 0; j < 4; j++) s[i][j] = 0.f;
        #pragma unroll 8
        for (int d = 0; d < 64; d++) {
            float a[4], bb[4];
            #pragma unroll
            for (int i = 0; i < 4; i++) a[i] = Qs[(r0 + i) * FPAD + d];
            #pragma unroll
            for (int j = 0; j < 4; j++) bb[j] = Ks[(c0 + j) * FPAD + d];
            #pragma unroll
            for (int i = 0; i < 4; i++)
                #pragma unroll
                for (int j = 0; j < 4; j++)
                    s[i][j] += a[i] * bb[j];
        }

        // online softmax per row (row owned by 16 threads sharing ty)
        #pragma unroll
        for (int i = 0; i < 4; i++) {
            float rmax = fmaxf(fmaxf(s[i][0], s[i][1]), fmaxf(s[i][2], s[i][3]));
            #pragma unroll
            for (int o = 8; o >= 1; o >>= 1)
                rmax = fmaxf(rmax, __shfl_xor_sync(0xffffffffu, rmax, o));
            float mnew = fmaxf(m_r[i], rmax);
            float alpha = __expf(m_r[i] - mnew);
            float rsum = 0.f;
            #pragma unroll
            for (int j = 0; j < 4; j++) {
                float p = __expf(s[i][j] - mnew);
                Ps[(r0 + i) * FPAD + c0 + j] = p;
                rsum += p;
            }
            #pragma unroll
            for (int o = 8; o >= 1; o >>= 1)
                rsum += __shfl_xor_sync(0xffffffffu, rsum, o);
            m_r[i] = mnew;
            l_r[i] = l_r[i] * alpha + rsum;
            #pragma unroll
            for (int j = 0; j < 4; j++) acc[i][j] *= alpha;
        }
        __syncthreads();

        // O += P @ V  (acc[i][j] = O[r0+i][c0+j], c0 now dim group)
        #pragma unroll 8
        for (int c = 0; c < 64; c++) {
            float pi[4], vv[4];
            #pragma unroll
            for (int i = 0; i < 4; i++) pi[i] = Ps[(r0 + i) * FPAD + c];
            #pragma unroll
            for (int j = 0; j < 4; j++) vv[j] = Vs[c * FPAD + c0 + j];
            #pragma unroll
            for (int i = 0; i < 4; i++)
                #pragma unroll
                for (int j = 0; j < 4; j++)
                    acc[i][j] += pi[i] * vv[j];
        }
    }

    #pragma unroll
    for (int i = 0; i < 4; i++) {
        float inv = 1.f / l_r[i];
        #pragma unroll
        for (int j = 0; j < 4; j++)
            O[(long)(r0 + i) * ors + c0 + j] = acc[i][j] * inv;
    }
}

extern "C" void kernel_launch(void* const* d_in, const int* in_sizes, int n_in,
                              void* d_out, int out_size) {
    const float* x         = (const float*)d_in[0];
    const float* w_qkv     = (const float*)d_in[1];
    const float* w_proj    = (const float*)d_in[2];
    const float* b_proj    = (const float*)d_in[3];
    const float* w_sr_conv = (const float*)d_in[4];
    const float* b_sr_conv = (const float*)d_in[5];
    const float* gam       = (const float*)d_in[6];
    const float* bet       = (const float*)d_in[7];
    const float* w_sr_lin  = (const float*)d_in[8];
    const float* b_sr_lin  = (const float*)d_in[9];
    float* out = (float*)d_out;

    float *qkv, *xnorm, *xr, *kc, *vc, *attn;
    cudaGetSymbolAddress((void**)&qkv,   g_qkv);
    cudaGetSymbolAddress((void**)&xnorm, g_xnorm);
    cudaGetSymbolAddress((void**)&xr,    g_xr);
    cudaGetSymbolAddress((void**)&kc,    g_kc);
    cudaGetSymbolAddress((void**)&vc,    g_vc);
    cudaGetSymbolAddress((void**)&attn,  g_attn);

    const int fsm = 4 * 64 * FPAD * (int)sizeof(float); // 66560 B
    cudaFuncSetAttribute((const void*)flash64,
                         cudaFuncAttributeMaxDynamicSharedMemorySize, fsm);

    // 1) QKV projection: [B*N, C] @ [C, 3C]
    gemm64<<<dim3(C3 / 64, (BB * NN) / 64), 256>>>(x, w_qkv, nullptr, qkv,
                                                   BB * NN, C3, CC);

    // 2) SR branch: depthwise conv + bias + LN, then linear [B*M, C]@[C, HD]+b
    sr_conv_ln<<<BB * MM, 128>>>(x, w_sr_conv, b_sr_conv, gam, bet, xnorm);
    gemm64<<<dim3(1, (BB * MM) / 64), 256>>>(xnorm, w_sr_lin, b_sr_lin, xr,
                                             BB * MM, HD, CC);

    // 3) k_c = Attn(x_, k, k)   [K = V = k slice of qkv]
    flash64<<<dim3(MM / 64, BB * HH), 256, fsm>>>(
        xr,       (long)MM * HD,      0L,             HD,
        qkv + CC, (long)NN * C3,      (long)HD,       C3,
        qkv + CC, (long)NN * C3,      (long)HD,       C3,
        kc,       (long)HH * MM * HD, (long)MM * HD,  HD,
        NN, 1.0f);

    // 4) v_c = Attn(x_, v, v)
    flash64<<<dim3(MM / 64, BB * HH), 256, fsm>>>(
        xr,             (long)MM * HD,      0L,            HD,
        qkv + 2 * CC,   (long)NN * C3,      (long)HD,      C3,
        qkv + 2 * CC,   (long)NN * C3,      (long)HD,      C3,
        vc,             (long)HH * MM * HD, (long)MM * HD, HD,
        NN, 1.0f);

    // 5) out = Attn(q * HD^-0.5, k_c, v_c)
    flash64<<<dim3(NN / 64, BB * HH), 256, fsm>>>(
        qkv,  (long)NN * C3,      (long)HD,      C3,
        kc,   (long)HH * MM * HD, (long)MM * HD, HD,
        vc,   (long)HH * MM * HD, (long)MM * HD, HD,
        attn, (long)NN * CC,      (long)HD,      CC,
        MM, 0.125f);

    // 6) Output projection: [B*N, C] @ [C, C] + b_proj
    gemm64<<<dim3(CC / 64, (BB * NN) / 64), 256>>>(attn, w_proj, b_proj, out,
                                                   BB * NN, CC, CC);
}

// round 3
// speedup vs baseline: 1.0001x; 1.0001x over previous
#include <cuda_runtime.h>

// Problem constants
#define BB 4
#define NN 4096
#define CC 512
#define HH 8
#define HD 64
#define MM 1024            // (64/2)^2 after spatial reduction
#define C3 1536

// ---- scratch (device globals; no allocations allowed) ----
__device__ float g_qkv[BB * NN * C3];     // [B,N,3C]
__device__ float g_xnorm[BB * MM * CC];   // conv+LN output [B,M,C]
__device__ float g_xr[BB * MM * HD];      // sr linear output [B,M,HD]
__device__ float g_kc[BB * HH * MM * HD]; // compressed K [B,H,M,HD]
__device__ float g_vc[BB * HH * MM * HD]; // compressed V [B,H,M,HD]
__device__ float g_attn[BB * NN * CC];    // attention out pre-proj [B,N,C]

// ============================================================
// Generic tiled SGEMM: C[M,N] = A[M,K] @ B[K,N] (+bias)
// BM=BN=64, BK=16, 256 threads, 4x4 per thread.
// M,N multiples of 64; K multiple of 16 (true for all calls here).
// ============================================================
__global__ void gemm64(const float* __restrict__ A, const float* __restrict__ B,
                       const float* __restrict__ bias, float* __restrict__ C,
                       int Md, int Nd, int Kd) {
    __shared__ float As[16][68];
    __shared__ float Bs[16][68];
    const int tx = threadIdx.x & 15;
    const int ty = threadIdx.x >> 4;
    const int rowBase = blockIdx.y * 64;
    const int colBase = blockIdx.x * 64;
    float acc[4][4] = {};

    for (int k0 = 0; k0 < Kd; k0 += 16) {
        #pragma unroll
        for (int t = threadIdx.x; t < 1024; t += 256) {
            int m = t >> 4, kk = t & 15;
            As[kk][m] = A[(long)(rowBase + m) * Kd + k0 + kk];
        }
        #pragma unroll
        for (int t = threadIdx.x; t < 1024; t += 256) {
            int kk = t >> 6, n = t & 63;
            Bs[kk][n] = B[(long)(k0 + kk) * Nd + colBase + n];
        }
        __syncthreads();
        #pragma unroll
        for (int kk = 0; kk < 16; kk++) {
            float a[4], b[4];
            #pragma unroll
            for (int i = 0; i < 4; i++) a[i] = As[kk][ty * 4 + i];
            #pragma unroll
            for (int j = 0; j < 4; j++) b[j] = Bs[kk][tx * 4 + j];
            #pragma unroll
            for (int i = 0; i < 4; i++)
                #pragma unroll
                for (int j = 0; j < 4; j++)
                    acc[i][j] += a[i] * b[j];
        }
        __syncthreads();
    }

    #pragma unroll
    for (int i = 0; i < 4; i++) {
        long r = rowBase + ty * 4 + i;
        #pragma unroll
        for (int j = 0; j < 4; j++) {
            int c = colBase + tx * 4 + j;
            float v = acc[i][j];
            if (bias) v += bias[c];
            C[r * Nd + c] = v;
        }
    }
}

// ============================================================
// Depthwise 2x2 stride-2 conv + bias + LayerNorm over C.
// One block per (b, m) output token; 128 threads, 4 channels each.
// Input x: [B, N=4096(=64x64 spatial), C]; output: [B, M=1024, C]
// ============================================================
__global__ void sr_conv_ln(const float* __restrict__ x, const float* __restrict__ wc,
                           const float* __restrict__ bc, const float* __restrict__ gam,
                           const float* __restrict__ bet, float* __restrict__ out) {
    const int bm = blockIdx.x;
    const int b = bm >> 10, m = bm & 1023;
    const int oi = m >> 5, oj = m & 31;
    // n00 = (2*oi)*64 + 2*oj
    const long base = ((long)b * NN + oi * 128 + oj * 2) * CC;
    __shared__ float red[4];
    const int tid = threadIdx.x; // 128 threads

    float y[4];
    float loc = 0.f;
    #pragma unroll
    for (int cc = 0; cc < 4; cc++) {
        int c = tid + cc * 128;
        float v = x[base + c]           * wc[c * 4 + 0]
                + x[base + CC + c]      * wc[c * 4 + 1]
                + x[base + 64 * CC + c] * wc[c * 4 + 2]
                + x[base + 65 * CC + c] * wc[c * 4 + 3]
                + bc[c];
        y[cc] = v;
        loc += v;
    }
    #pragma unroll
    for (int o = 16; o >= 1; o >>= 1) loc += __shfl_xor_sync(0xffffffffu, loc, o);
    if ((tid & 31) == 0) red[tid >> 5] = loc;
    __syncthreads();
    float mu = (red[0] + red[1] + red[2] + red[3]) * (1.f / 512.f);

    float lv = 0.f;
    #pragma unroll
    for (int cc = 0; cc < 4; cc++) { float d = y[cc] - mu; lv += d * d; }
    #pragma unroll
    for (int o = 16; o >= 1; o >>= 1) lv += __shfl_xor_sync(0xffffffffu, lv, o);
    __syncthreads();
    if ((tid & 31) == 0) red[tid >> 5] = lv;
    __syncthreads();
    float var = (red[0] + red[1] + red[2] + red[3]) * (1.f / 512.f);
    float inv = rsqrtf(var + 1e-5f);

    long ob = ((long)b * MM + m) * CC;
    #pragma unroll
    for (int cc = 0; cc < 4; cc++) {
        int c = tid + cc * 128;
        out[ob + c] = (y[cc] - mu) * inv * gam[c] + bet[c];
    }
}

// ============================================================
// Generic flash attention, HD=64, BM=BN=64, 256 threads.
// Per (b,h): O = softmax(scale * Q @ K^T) @ V with online softmax.
// Pointers addressed as base + b*bs + h*hs + row*rs (+ d).
// nq, nk must be multiples of 64 (they are: 1024/4096).
// ============================================================
#define FPAD 65
__global__ void flash64(
    const float* __restrict__ Qb, long qbs, long qhs, int qrs,
    const float* __restrict__ Kb, long kbs, long khs, int krs,
    const float* __restrict__ Vb, long vbs, long vhs, int vrs,
    float* __restrict__ Ob, long obs, long ohs, int ors,
    int nk, float scale) {
    extern __shared__ float smf[];
    float* Qs = smf;                 // [64][65]
    float* Ks = smf + 64 * FPAD;
    float* Vs = smf + 2 * 64 * FPAD;
    float* Ps = smf + 3 * 64 * FPAD;

    const int bh = blockIdx.y;
    const int b = bh >> 3, h = bh & 7;
    const float* Q = Qb + b * qbs + h * qhs + (long)blockIdx.x * 64 * qrs;
    const float* K = Kb + b * kbs + h * khs;
    const float* V = Vb + b * vbs + h * vhs;
    float*       O = Ob + b * obs + h * ohs + (long)blockIdx.x * 64 * ors;

    const int tx = threadIdx.x & 15;   // column group (keys for S, dims for O)
    const int ty = threadIdx.x >> 4;   // row group (queries)
    const int r0 = ty * 4;
    const int c0 = tx * 4;

    // load Q tile (scaled)
    for (int t = threadIdx.x; t < 4096; t += 256) {
        int r = t >> 6, d = t & 63;
        Qs[r * FPAD + d] = Q[(long)r * qrs + d] * scale;
    }

    float m_r[4], l_r[4], acc[4][4];
    #pragma unroll
    for (int i = 0; i < 4; i++) {
        m_r[i] = -1e30f; l_r[i] = 0.f;
        #pragma unroll
        for (int j = 0; j < 4; j++) acc[i][j] = 0.f;
    }

    for (int kt = 0; kt < nk; kt += 64) {
        __syncthreads();  // protect Qs (first iter) and Ks/Vs/Ps reuse
        for (int t = threadIdx.x; t < 4096; t += 256) {
            int r = t >> 6, d = t & 63;
            Ks[r * FPAD + d] = K[(long)(kt + r) * krs + d];
            Vs[r * FPAD + d] = V[(long)(kt + r) * vrs + d];
        }
        __syncthreads();

        // S = Qtile @ Ktile^T, 4x4 per thread
        float s[4][4];
        #pragma unroll
        for (int i = 0; i < 4; i++)
            #pragma unroll
            for (int j = 0; j < 4; j++) s[i][j] = 0.f;
        #pragma unroll 8
        for (int d = 0; d < 64; d++) {
            float a[4], bb[4];
            #pragma unroll
            for (int i = 0; i < 4; i++) a[i] = Qs[(r0 + i) * FPAD + d];
            #pragma unroll
            for (int j = 0; j < 4; j++) bb[j] = Ks[(c0 + j) * FPAD + d];
            #pragma unroll
            for (int i = 0; i < 4; i++)
                #pragma unroll
                for (int j = 0; j < 4; j++)
                    s[i][j] += a[i] * bb[j];
        }

        // online softmax per row (row owned by 16 threads sharing ty)
        #pragma unroll
        for (int i = 0; i < 4; i++) {
            float rmax = fmaxf(fmaxf(s[i][0], s[i][1]), fmaxf(s[i][2], s[i][3]));
            #pragma unroll
            for (int o = 8; o >= 1; o >>= 1)
                rmax = fmaxf(rmax, __shfl_xor_sync(0xffffffffu, rmax, o));
            float mnew = fmaxf(m_r[i], rmax);
            float alpha = __expf(m_r[i] - mnew);
            float rsum = 0.f;
            #pragma unroll
            for (int j = 0; j < 4; j++) {
                float p = __expf(s[i][j] - mnew);
                Ps[(r0 + i) * FPAD + c0 + j] = p;
                rsum += p;
            }
            #pragma unroll
            for (int o = 8; o >= 1; o >>= 1)
                rsum += __shfl_xor_sync(0xffffffffu, rsum, o);
            m_r[i] = mnew;
            l_r[i] = l_r[i] * alpha + rsum;
            #pragma unroll
            for (int j = 0; j < 4; j++) acc[i][j] *= alpha;
        }
        __syncthreads();

        // O += P @ V  (acc[i][j] = O[r0+i][c0+j], c0 now dim group)
        #pragma unroll 8
        for (int c = 0; c < 64; c++) {
            float pi[4], vv[4];
            #pragma unroll
            for (int i = 0; i < 4; i++) pi[i] = Ps[(r0 + i) * FPAD + c];
            #pragma unroll
            for (int j = 0; j < 4; j++) vv[j] = Vs[c * FPAD + c0 + j];
            #pragma unroll
            for (int i = 0; i < 4; i++)
                #pragma unroll
                for (int j = 0; j < 4; j++)
                    acc[i][j] += pi[i] * vv[j];
        }
    }

    #pragma unroll
    for (int i = 0; i < 4; i++) {
        float inv = 1.f / l_r[i];
        #pragma unroll
        for (int j = 0; j < 4; j++)
            O[(long)(r0 + i) * ors + c0 + j] = acc[i][j] * inv;
    }
}

extern "C" void kernel_launch(void* const* d_in, const int* in_sizes, int n_in,
                              void* d_out, int out_size) {
    const float* x         = (const float*)d_in[0];
    const float* w_qkv     = (const float*)d_in[1];
    const float* w_proj    = (const float*)d_in[2];
    const float* b_proj    = (const float*)d_in[3];
    const float* w_sr_conv = (const float*)d_in[4];
    const float* b_sr_conv = (const float*)d_in[5];
    const float* gam       = (const float*)d_in[6];
    const float* bet       = (const float*)d_in[7];
    const float* w_sr_lin  = (const float*)d_in[8];
    const float* b_sr_lin  = (const float*)d_in[9];
    float* out = (float*)d_out;

    float *qkv, *xnorm, *xr, *kc, *vc, *attn;
    cudaGetSymbolAddress((void**)&qkv,   g_qkv);
    cudaGetSymbolAddress((void**)&xnorm, g_xnorm);
    cudaGetSymbolAddress((void**)&xr,    g_xr);
    cudaGetSymbolAddress((void**)&kc,    g_kc);
    cudaGetSymbolAddress((void**)&vc,    g_vc);
    cudaGetSymbolAddress((void**)&attn,  g_attn);

    const int fsm = 4 * 64 * FPAD * (int)sizeof(float); // 66560 B
    cudaFuncSetAttribute((const void*)flash64,
                         cudaFuncAttributeMaxDynamicSharedMemorySize, fsm);

    // 1) QKV projection: [B*N, C] @ [C, 3C]
    gemm64<<<dim3(C3 / 64, (BB * NN) / 64), 256>>>(x, w_qkv, nullptr, qkv,
                                                   BB * NN, C3, CC);

    // 2) SR branch: depthwise conv + bias + LN, then linear [B*M, C]@[C, HD]+b
    sr_conv_ln<<<BB * MM, 128>>>(x, w_sr_conv, b_sr_conv, gam, bet, xnorm);
    gemm64<<<dim3(1, (BB * MM) / 64), 256>>>(xnorm, w_sr_lin, b_sr_lin, xr,
                                             BB * MM, HD, CC);

    // 3) k_c = Attn(x_, k, k)   [K = V = k slice of qkv]
    flash64<<<dim3(MM / 64, BB * HH), 256, fsm>>>(
        xr,       (long)MM * HD,      0L,             HD,
        qkv + CC, (long)NN * C3,      (long)HD,       C3,
        qkv + CC, (long)NN * C3,      (long)HD,       C3,
        kc,       (long)HH * MM * HD, (long)MM * HD,  HD,
        NN, 1.0f);

    // 4) v_c = Attn(x_, v, v)
    flash64<<<dim3(MM / 64, BB * HH), 256, fsm>>>(
        xr,             (long)MM * HD,      0L,            HD,
        qkv + 2 * CC,   (long)NN * C3,      (long)HD,      C3,
        qkv + 2 * CC,   (long)NN * C3,      (long)HD,      C3,
        vc,             (long)HH * MM * HD, (long)MM * HD, HD,
        NN, 1.0f);

    // 5) out = Attn(q * HD^-0.5, k_c, v_c)
    flash64<<<dim3(NN / 64, BB * HH), 256, fsm>>>(
        qkv,  (long)NN * C3,      (long)HD,      C3,
        kc,   (long)HH * MM * HD, (long)MM * HD, HD,
        vc,   (long)HH * MM * HD, (long)MM * HD, HD,
        attn, (long)NN * CC,      (long)HD,      CC,
        MM, 0.125f);

    // 6) Output projection: [B*N, C] @ [C, C] + b_proj
    gemm64<<<dim3(CC / 64, (BB * NN) / 64), 256>>>(attn, w_proj, b_proj, out,
                                                   BB * NN, CC, CC);
}

// round 7
// speedup vs baseline: 2.3884x; 2.3882x over previous
#include <cuda_runtime.h>
#include <cuda_bf16.h>
#include <cstdint>

#define BB 4
#define NN 4096
#define CC 512
#define HH 8
#define HD 64
#define MM 1024
#define C3 1536
#define BHZ (BB*HH)

typedef __nv_bfloat16 bf16;

__device__ float g_qkv   [BB*NN*C3];
__device__ bf16  g_qkv_h [BB*NN*C3];
__device__ bf16  g_qkv_l [BB*NN*C3];
__device__ bf16  g_x_h   [BB*NN*CC];
__device__ bf16  g_x_l   [BB*NN*CC];
__device__ bf16  g_wqT_h [C3*CC];
__device__ bf16  g_wqT_l [C3*CC];
__device__ bf16  g_wpT_h [CC*CC];
__device__ bf16  g_wpT_l [CC*CC];
__device__ float g_xnorm [BB*MM*CC];
__device__ float g_xr    [BB*MM*HD];
__device__ bf16  g_xr_h  [BB*MM*HD];
__device__ bf16  g_xr_l  [BB*MM*HD];
__device__ bf16  g_kT_h  [BHZ*HD*NN];
__device__ bf16  g_kT_l  [BHZ*HD*NN];
__device__ bf16  g_vT_h  [BHZ*HD*NN];
__device__ bf16  g_vT_l  [BHZ*HD*NN];
__device__ float g_S     [134217728];
__device__ bf16  g_P_h   [134217728];
__device__ bf16  g_P_l   [134217728];
__device__ float g_kc    [BHZ*MM*HD];
__device__ bf16  g_kc_h  [BHZ*MM*HD];
__device__ bf16  g_kc_l  [BHZ*MM*HD];
__device__ float g_vc    [BHZ*MM*HD];
__device__ bf16  g_vcT_h [BHZ*HD*MM];
__device__ bf16  g_vcT_l [BHZ*HD*MM];
__device__ float g_attn  [BB*NN*CC];
__device__ bf16  g_at_h  [BB*NN*CC];
__device__ bf16  g_at_l  [BB*NN*CC];

__device__ __forceinline__ uint32_t smem_u32(const void* p) {
    uint32_t a;
    asm("{ .reg .u64 t; cvta.to.shared.u64 t, %1; cvt.u32.u64 %0, t; }" : "=r"(a) : "l"(p));
    return a;
}
__device__ __forceinline__ void cp16(uint32_t s, const void* g) {
    asm volatile("cp.async.cg.shared.global [%0], [%1], 16;" :: "r"(s), "l"(g));
}
__device__ __forceinline__ void ldsm4(uint32_t& r0, uint32_t& r1, uint32_t& r2, uint32_t& r3, uint32_t a) {
    asm volatile("ldmatrix.sync.aligned.m8n8.x4.shared.b16 {%0,%1,%2,%3}, [%4];"
                 : "=r"(r0), "=r"(r1), "=r"(r2), "=r"(r3) : "r"(a));
}
#define MMA(c, a, b) \
    asm volatile("mma.sync.aligned.m16n8k16.row.col.f32.bf16.bf16.f32 " \
        "{%0,%1,%2,%3}, {%4,%5,%6,%7}, {%8,%9}, {%0,%1,%2,%3};" \
        : "+f"((c)[0]), "+f"((c)[1]), "+f"((c)[2]), "+f"((c)[3]) \
        : "r"((a)[0]), "r"((a)[1]), "r"((a)[2]), "r"((a)[3]), "r"((b)[0]), "r"((b)[1]))

__device__ __forceinline__ uint32_t pk(float a, float b) {
    unsigned short ua = __bfloat16_as_ushort(__float2bfloat16(a));
    unsigned short ub = __bfloat16_as_ushort(__float2bfloat16(b));
    return (uint32_t)ua | ((uint32_t)ub << 16);
}
__device__ __forceinline__ float bres(float a) {
    return a - __bfloat162float(__float2bfloat16(a));
}

// ============================================================
// batched NT GEMM with split-bf16 3-MMA via mma.sync (HMMA):
// D[z] = A[z] @ B[z]^T (+bias), A=Ah+Al, B=Bh+Bl.
// Tile 128 x BN x 64, 256 threads (8 warps, 4m x 2n), cp.async 2-stage.
// B tiles are [n][k] row-major == col-major k x n, so B uses NON-trans
// ldmatrix (fragment: thread t -> B_mem[n=t>>2][k=2*(t&3)+e]).
// ============================================================
template<int BN>
__global__ void __launch_bounds__(256, 1)
gemm_mma(const bf16* __restrict__ Ah, const bf16* __restrict__ Al,
         int lda, long Azb, long Azh,
         const bf16* __restrict__ Bh, const bf16* __restrict__ Bl,
         int ldb, long Bzb, long Bzh,
         float* __restrict__ D, int ldd, long Dzb, long Dzh,
         const float* __restrict__ bias, int K, int Hdiv)
{
    constexpr int NT  = BN / 16;
    constexpr int ATB = 128 * 128;
    constexpr int BTB = BN * 128;
    constexpr int BUF = 2 * ATB + 2 * BTB;
    extern __shared__ __align__(128) char smc[];
    const uint32_t sb = smem_u32(smc);

    const int tid = threadIdx.x, lane = tid & 31, wid = tid >> 5;
    const int wm = (wid & 3) * 32, wn = (wid >> 2) * (BN / 2);
    const int z = blockIdx.z, zbq = z / Hdiv, zhq = z % Hdiv;

    const long aoff = (long)zbq * Azb + (long)zhq * Azh + (long)(blockIdx.y * 128) * lda;
    const long boff = (long)zbq * Bzb + (long)zhq * Bzh + (long)(blockIdx.x * BN) * ldb;
    const bf16* Agh = Ah + aoff;  const bf16* Agl = Al + aoff;
    const bf16* Bgh = Bh + boff;  const bf16* Bgl = Bl + boff;

    float cacc[2][NT][4];
    #pragma unroll
    for (int i = 0; i < 2; i++)
        #pragma unroll
        for (int j = 0; j < NT; j++)
            #pragma unroll
            for (int t = 0; t < 4; t++) cacc[i][j][t] = 0.f;

    auto ldA = [&](int buf, int ch) {
        const bf16* s0 = Agh + ch * 64;
        const bf16* s1 = Agl + ch * 64;
        uint32_t base = sb + buf * BUF;
        #pragma unroll
        for (int i = 0; i < 4; i++) {
            int idx = tid + i * 256;
            int r = idx >> 3, c = idx & 7;
            uint32_t d = base + r * 128 + ((c ^ (r & 7)) * 16);
            cp16(d,       s0 + (long)r * lda + c * 8);
            cp16(d + ATB, s1 + (long)r * lda + c * 8);
        }
    };
    auto ldB = [&](int buf, int ch) {
        const bf16* s0 = Bgh + ch * 64;
        const bf16* s1 = Bgl + ch * 64;
        uint32_t base = sb + buf * BUF + 2 * ATB;
        #pragma unroll
        for (int i = 0; i < (BN * 8) / 256; i++) {
            int idx = tid + i * 256;
            int r = idx >> 3, c = idx & 7;
            uint32_t d = base + r * 128 + ((c ^ (r & 7)) * 16);
            cp16(d,       s0 + (long)r * ldb + c * 8);
            cp16(d + BTB, s1 + (long)r * ldb + c * 8);
        }
    };

    const int arow = lane & 15;
    const int asel = lane >> 4;
    const int brow = ((lane >> 4) << 3) | (lane & 7);
    const int bsel = (lane >> 3) & 1;

    auto compute = [&](int buf) {
        const uint32_t ab = sb + buf * BUF;
        const uint32_t bbs = ab + 2 * ATB;
        #pragma unroll
        for (int ks = 0; ks < 4; ks++) {
            uint32_t ahf[2][4], alf[2][4], bhf[NT][2], blf[NT][2];
            #pragma unroll
            for (int mt = 0; mt < 2; mt++) {
                int row = wm + mt * 16 + arow;
                int c = ks * 2 + asel, ph = c ^ (row & 7);
                uint32_t ad = ab + row * 128 + ph * 16;
                ldsm4(ahf[mt][0], ahf[mt][1], ahf[mt][2], ahf[mt][3], ad);
                ldsm4(alf[mt][0], alf[mt][1], alf[mt][2], alf[mt][3], ad + ATB);
            }
            #pragma unroll
            for (int p = 0; p < NT / 2; p++) {
                int row = wn + p * 16 + brow;
                int c = ks * 2 + bsel, ph = c ^ (row & 7);
                uint32_t bd = bbs + row * 128 + ph * 16;
                ldsm4(bhf[2*p][0], bhf[2*p][1], bhf[2*p+1][0], bhf[2*p+1][1], bd);
                ldsm4(blf[2*p][0], blf[2*p][1], blf[2*p+1][0], blf[2*p+1][1], bd + BTB);
            }
            #pragma unroll
            for (int mt = 0; mt < 2; mt++)
                #pragma unroll
                for (int nt = 0; nt < NT; nt++) {
                    MMA(cacc[mt][nt], ahf[mt], bhf[nt]);
                    MMA(cacc[mt][nt], ahf[mt], blf[nt]);
                    MMA(cacc[mt][nt], alf[mt], bhf[nt]);
                }
        }
    };

    const int nch = K >> 6;
    ldA(0, 0); ldB(0, 0);
    asm volatile("cp.async.commit_group;" ::: "memory");
    asm volatile("cp.async.wait_group 0;" ::: "memory");
    __syncthreads();
    for (int ch = 0; ch < nch; ch++) {
        int buf = ch & 1;
        if (ch + 1 < nch) {
            ldA(buf ^ 1, ch + 1); ldB(buf ^ 1, ch + 1);
            asm volatile("cp.async.commit_group;" ::: "memory");
        }
        compute(buf);
        if (ch + 1 < nch) {
            asm volatile("cp.async.wait_group 0;" ::: "memory");
            __syncthreads();
        }
    }

    float* Dp = D + (long)zbq * Dzb + (long)zhq * Dzh;
    const int g = lane >> 2, tg = lane & 3;
    #pragma unroll
    for (int mt = 0; mt < 2; mt++) {
        long r0 = (long)(blockIdx.y * 128 + wm + mt * 16 + g);
        #pragma unroll
        for (int nt = 0; nt < NT; nt++) {
            int col = blockIdx.x * BN + wn + nt * 8 + tg * 2;
            float b0 = bias ? bias[col] : 0.f;
            float b1 = bias ? bias[col + 1] : 0.f;
            float2 v0 = { cacc[mt][nt][0] + b0, cacc[mt][nt][1] + b1 };
            float2 v1 = { cacc[mt][nt][2] + b0, cacc[mt][nt][3] + b1 };
            *(float2*)(Dp + r0 * ldd + col)       = v0;
            *(float2*)(Dp + (r0 + 8) * ldd + col) = v1;
        }
    }
}

__global__ void k_split(const float* __restrict__ in, bf16* __restrict__ oh,
                        bf16* __restrict__ ol, long n) {
    long idx = ((long)blockIdx.x * blockDim.x + threadIdx.x) * 4;
    if (idx >= n) return;
    float4 f = *(const float4*)(in + idx);
    uint2 uh; uh.x = pk(f.x, f.y); uh.y = pk(f.z, f.w);
    uint2 ul; ul.x = pk(bres(f.x), bres(f.y)); ul.y = pk(bres(f.z), bres(f.w));
    *(uint2*)(oh + idx) = uh;
    *(uint2*)(ol + idx) = ul;
}

__global__ void k_trsplit(const float* __restrict__ in, int ldin, long izb, long izh, int Hdiv,
                          bf16* __restrict__ oh, bf16* __restrict__ ol,
                          int ldout, long ozs) {
    __shared__ float t[32][33];
    const int z = blockIdx.z;
    const float* ip = in + (long)(z / Hdiv) * izb + (long)(z % Hdiv) * izh;
    const int r0 = blockIdx.x * 32, c0 = blockIdx.y * 32;
    const int tx = threadIdx.x & 31, ty = threadIdx.x >> 5;
    #pragma unroll
    for (int i = 0; i < 4; i++) {
        int r = ty + i * 8;
        t[r][tx] = ip[(long)(r0 + r) * ldin + c0 + tx];
    }
    __syncthreads();
    bf16* ohp = oh + (long)z * ozs;
    bf16* olp = ol + (long)z * ozs;
    #pragma unroll
    for (int i = 0; i < 4; i++) {
        int oc = ty + i * 8;
        float f = t[tx][oc];
        long o = (long)(c0 + oc) * ldout + r0 + tx;
        ohp[o] = __float2bfloat16(f);
        olp[o] = __float2bfloat16(bres(f));
    }
}

template<int VPT>
__global__ void k_softmax(const float* __restrict__ S, bf16* __restrict__ Ph,
                          bf16* __restrict__ Pl, float scale) {
    const int cols = VPT * 256;
    const long base = (long)blockIdx.x * cols;
    const float* sp = S + base;
    const int tid = threadIdx.x;
    __shared__ float red[8];
    float v[VPT];
    float mx = -1e30f;
    #pragma unroll
    for (int i = 0; i < VPT / 4; i++) {
        float4 f = *(const float4*)(sp + (i * 256 + tid) * 4);
        v[i*4+0] = f.x * scale; v[i*4+1] = f.y * scale;
        v[i*4+2] = f.z * scale; v[i*4+3] = f.w * scale;
        mx = fmaxf(mx, fmaxf(fmaxf(v[i*4], v[i*4+1]), fmaxf(v[i*4+2], v[i*4+3])));
    }
    #pragma unroll
    for (int o = 16; o >= 1; o >>= 1) mx = fmaxf(mx, __shfl_xor_sync(0xffffffffu, mx, o));
    if ((tid & 31) == 0) red[tid >> 5] = mx;
    __syncthreads();
    float bm = red[0];
    #pragma unroll
    for (int i = 1; i < 8; i++) bm = fmaxf(bm, red[i]);
    __syncthreads();
    float s = 0.f;
    #pragma unroll
    for (int j = 0; j < VPT; j++) { v[j] = __expf(v[j] - bm); s += v[j]; }
    #pragma unroll
    for (int o = 16; o >= 1; o >>= 1) s += __shfl_xor_sync(0xffffffffu, s, o);
    if ((tid & 31) == 0) red[tid >> 5] = s;
    __syncthreads();
    float bs = 0.f;
    #pragma unroll
    for (int i = 0; i < 8; i++) bs += red[i];
    float inv = 1.f / bs;
    #pragma unroll
    for (int i = 0; i < VPT / 4; i++) {
        long idx = base + (i * 256 + tid) * 4;
        float p0 = v[i*4+0] * inv, p1 = v[i*4+1] * inv;
        float p2 = v[i*4+2] * inv, p3 = v[i*4+3] * inv;
        uint2 uh; uh.x = pk(p0, p1); uh.y = pk(p2, p3);
        uint2 ul; ul.x = pk(bres(p0), bres(p1)); ul.y = pk(bres(p2), bres(p3));
        *(uint2*)(Ph + idx) = uh;
        *(uint2*)(Pl + idx) = ul;
    }
}

__global__ void gemm64(const float* __restrict__ A, const float* __restrict__ B,
                       const float* __restrict__ bias, float* __restrict__ C,
                       int Md, int Nd, int Kd) {
    __shared__ float As[16][68];
    __shared__ float Bs[16][68];
    const int tx = threadIdx.x & 15;
    const int ty = threadIdx.x >> 4;
    const int rowBase = blockIdx.y * 64;
    const int colBase = blockIdx.x * 64;
    float acc[4][4] = {};
    for (int k0 = 0; k0 < Kd; k0 += 16) {
        for (int t = threadIdx.x; t < 1024; t += 256) {
            int m = t >> 4, kk = t & 15;
            As[kk][m] = A[(long)(rowBase + m) * Kd + k0 + kk];
        }
        for (int t = threadIdx.x; t < 1024; t += 256) {
            int kk = t >> 6, n = t & 63;
            Bs[kk][n] = B[(long)(k0 + kk) * Nd + colBase + n];
        }
        __syncthreads();
        #pragma unroll
        for (int kk = 0; kk < 16; kk++) {
            float a[4], b[4];
            #pragma unroll
            for (int i = 0; i < 4; i++) a[i] = As[kk][ty * 4 + i];
            #pragma unroll
            for (int j = 0; j < 4; j++) b[j] = Bs[kk][tx * 4 + j];
            #pragma unroll
            for (int i = 0; i < 4; i++)
                #pragma unroll
                for (int j = 0; j < 4; j++) acc[i][j] += a[i] * b[j];
        }
        __syncthreads();
    }
    #pragma unroll
    for (int i = 0; i < 4; i++) {
        long r = rowBase + ty * 4 + i;
        #pragma unroll
        for (int j = 0; j < 4; j++) {
            int c = colBase + tx * 4 + j;
            float v = acc[i][j];
            if (bias) v += bias[c];
            C[r * Nd + c] = v;
        }
    }
}

__global__ void sr_conv_ln(const float* __restrict__ x, const float* __restrict__ wc,
                           const float* __restrict__ bc, const float* __restrict__ gam,
                           const float* __restrict__ bet, float* __restrict__ out) {
    const int bm = blockIdx.x;
    const int b = bm >> 10, m = bm & 1023;
    const int oi = m >> 5, oj = m & 31;
    const long base = ((long)b * NN + oi * 128 + oj * 2) * CC;
    __shared__ float red[4];
    const int tid = threadIdx.x;
    float y[4];
    float loc = 0.f;
    #pragma unroll
    for (int cc = 0; cc < 4; cc++) {
        int c = tid + cc * 128;
        float v = x[base + c]           * wc[c * 4 + 0]
                + x[base + CC + c]      * wc[c * 4 + 1]
                + x[base + 64 * CC + c] * wc[c * 4 + 2]
                + x[base + 65 * CC + c] * wc[c * 4 + 3]
                + bc[c];
        y[cc] = v; loc += v;
    }
    #pragma unroll
    for (int o = 16; o >= 1; o >>= 1) loc += __shfl_xor_sync(0xffffffffu, loc, o);
    if ((tid & 31) == 0) red[tid >> 5] = loc;
    __syncthreads();
    float mu = (red[0] + red[1] + red[2] + red[3]) * (1.f / 512.f);
    float lv = 0.f;
    #pragma unroll
    for (int cc = 0; cc < 4; cc++) { float d = y[cc] - mu; lv += d * d; }
    #pragma unroll
    for (int o = 16; o >= 1; o >>= 1) lv += __shfl_xor_sync(0xffffffffu, lv, o);
    __syncthreads();
    if ((tid & 31) == 0) red[tid >> 5] = lv;
    __syncthreads();
    float var = (red[0] + red[1] + red[2] + red[3]) * (1.f / 512.f);
    float inv = rsqrtf(var + 1e-5f);
    long ob = ((long)b * MM + m) * CC;
    #pragma unroll
    for (int cc = 0; cc < 4; cc++) {
        int c = tid + cc * 128;
        out[ob + c] = (y[cc] - mu) * inv * gam[c] + bet[c];
    }
}

extern "C" void kernel_launch(void* const* d_in, const int* in_sizes, int n_in,
                              void* d_out, int out_size) {
    const float* x         = (const float*)d_in[0];
    const float* w_qkv     = (const float*)d_in[1];
    const float* w_proj    = (const float*)d_in[2];
    const float* b_proj    = (const float*)d_in[3];
    const float* w_sr_conv = (const float*)d_in[4];
    const float* b_sr_conv = (const float*)d_in[5];
    const float* gam       = (const float*)d_in[6];
    const float* bet       = (const float*)d_in[7];
    const float* w_sr_lin  = (const float*)d_in[8];
    const float* b_sr_lin  = (const float*)d_in[9];
    float* out = (float*)d_out;

    float *qkv, *xnorm, *xr, *kc, *vc, *attn, *S;
    bf16 *qkv_h,*qkv_l,*x_h,*x_l,*wqT_h,*wqT_l,*wpT_h,*wpT_l;
    bf16 *xr_h,*xr_l,*kT_h,*kT_l,*vT_h,*vT_l,*P_h,*P_l;
    bf16 *kc_h,*kc_l,*vcT_h,*vcT_l,*at_h,*at_l;
    cudaGetSymbolAddress((void**)&qkv,   g_qkv);
    cudaGetSymbolAddress((void**)&qkv_h, g_qkv_h);
    cudaGetSymbolAddress((void**)&qkv_l, g_qkv_l);
    cudaGetSymbolAddress((void**)&x_h,   g_x_h);
    cudaGetSymbolAddress((void**)&x_l,   g_x_l);
    cudaGetSymbolAddress((void**)&wqT_h, g_wqT_h);
    cudaGetSymbolAddress((void**)&wqT_l, g_wqT_l);
    cudaGetSymbolAddress((void**)&wpT_h, g_wpT_h);
    cudaGetSymbolAddress((void**)&wpT_l, g_wpT_l);
    cudaGetSymbolAddress((void**)&xnorm, g_xnorm);
    cudaGetSymbolAddress((void**)&xr,    g_xr);
    cudaGetSymbolAddress((void**)&xr_h,  g_xr_h);
    cudaGetSymbolAddress((void**)&xr_l,  g_xr_l);
    cudaGetSymbolAddress((void**)&kT_h,  g_kT_h);
    cudaGetSymbolAddress((void**)&kT_l,  g_kT_l);
    cudaGetSymbolAddress((void**)&vT_h,  g_vT_h);
    cudaGetSymbolAddress((void**)&vT_l,  g_vT_l);
    cudaGetSymbolAddress((void**)&S,     g_S);
    cudaGetSymbolAddress((void**)&P_h,   g_P_h);
    cudaGetSymbolAddress((void**)&P_l,   g_P_l);
    cudaGetSymbolAddress((void**)&kc,    g_kc);
    cudaGetSymbolAddress((void**)&kc_h,  g_kc_h);
    cudaGetSymbolAddress((void**)&kc_l,  g_kc_l);
    cudaGetSymbolAddress((void**)&vc,    g_vc);
    cudaGetSymbolAddress((void**)&vcT_h, g_vcT_h);
    cudaGetSymbolAddress((void**)&vcT_l, g_vcT_l);
    cudaGetSymbolAddress((void**)&attn,  g_attn);
    cudaGetSymbolAddress((void**)&at_h,  g_at_h);
    cudaGetSymbolAddress((void**)&at_l,  g_at_l);

    const int SM128 = 2 * (2 * 128 * 128 + 2 * 128 * 128);
    const int SM64  = 2 * (2 * 128 * 128 + 2 * 64 * 128);
    cudaFuncSetAttribute((const void*)gemm_mma<128>,
                         cudaFuncAttributeMaxDynamicSharedMemorySize, SM128);
    cudaFuncSetAttribute((const void*)gemm_mma<64>,
                         cudaFuncAttributeMaxDynamicSharedMemorySize, SM64);

    const long NC3 = (long)NN * C3;

    k_split<<<8192, 256>>>(x, x_h, x_l, (long)BB * NN * CC);
    k_trsplit<<<dim3(16, 48, 1), 256>>>(w_qkv, C3, 0, 0, 1, wqT_h, wqT_l, CC, 0);
    k_trsplit<<<dim3(16, 16, 1), 256>>>(w_proj, CC, 0, 0, 1, wpT_h, wpT_l, CC, 0);

    // QKV projection
    gemm_mma<128><<<dim3(12, 128, 1), 256, SM128>>>(
        x_h, x_l, CC, 0, 0,  wqT_h, wqT_l, CC, 0, 0,
        qkv, C3, 0, 0, nullptr, CC, 1);

    // SR branch
    sr_conv_ln<<<BB * MM, 128>>>(x, w_sr_conv, b_sr_conv, gam, bet, xnorm);
    gemm64<<<dim3(1, (BB * MM) / 64), 256>>>(xnorm, w_sr_lin, b_sr_lin, xr, BB * MM, HD, CC);
    k_split<<<256, 256>>>(xr, xr_h, xr_l, (long)BB * MM * HD);

    k_split<<<24576, 256>>>(qkv, qkv_h, qkv_l, (long)BB * NN * C3);
    k_trsplit<<<dim3(128, 2, 32), 256>>>(qkv + CC,     C3, NC3, HD, HH, kT_h, kT_l, NN, (long)HD * NN);
    k_trsplit<<<dim3(128, 2, 32), 256>>>(qkv + 2 * CC, C3, NC3, HD, HH, vT_h, vT_l, NN, (long)HD * NN);

    // pooling attention 1: kc = softmax(x_ k^T) k
    gemm_mma<128><<<dim3(32, 8, 32), 256, SM128>>>(
        xr_h, xr_l, HD, (long)MM * HD, 0,
        qkv_h + CC, qkv_l + CC, C3, NC3, HD,
        S, NN, 8L * MM * NN, (long)MM * NN, nullptr, HD, HH);
    k_softmax<16><<<BHZ * MM, 256>>>(S, P_h, P_l, 1.0f);
    gemm_mma<64><<<dim3(1, 8, 32), 256, SM64>>>(
        P_h, P_l, NN, (long)MM * NN, 0,
        kT_h, kT_l, NN, (long)HD * NN, 0,
        kc, HD, (long)MM * HD, 0, nullptr, NN, 1);
    k_split<<<2048, 256>>>(kc, kc_h, kc_l, (long)BHZ * MM * HD);

    // pooling attention 2: vc = softmax(x_ v^T) v
    gemm_mma<128><<<dim3(32, 8, 32), 256, SM128>>>(
        xr_h, xr_l, HD, (long)MM * HD, 0,
        qkv_h + 2 * CC, qkv_l + 2 * CC, C3, NC3, HD,
        S, NN, 8L * MM * NN, (long)MM * NN, nullptr, HD, HH);
    k_softmax<16><<<BHZ * MM, 256>>>(S, P_h, P_l, 1.0f);
    gemm_mma<64><<<dim3(1, 8, 32), 256, SM64>>>(
        P_h, P_l, NN, (long)MM * NN, 0,
        vT_h, vT_l, NN, (long)HD * NN, 0,
        vc, HD, (long)MM * HD, 0, nullptr, NN, 1);
    k_trsplit<<<dim3(32, 2, 32), 256>>>(vc, HD, (long)MM * HD, 0, 1, vcT_h, vcT_l, MM, (long)HD * MM);

    // main attention: attn = softmax(q kc^T * scale) vc
    gemm_mma<128><<<dim3(8, 32, 32), 256, SM128>>>(
        qkv_h, qkv_l, C3, NC3, HD,
        kc_h, kc_l, HD, 8L * MM * HD, (long)MM * HD,
        S, MM, 8L * NN * MM, (long)NN * MM, nullptr, HD, HH);
    k_softmax<4><<<BHZ * NN, 256>>>(S, P_h, P_l, 0.125f);
    gemm_mma<64><<<dim3(1, 32, 32), 256, SM64>>>(
        P_h, P_l, MM, 8L * NN * MM, (long)NN * MM,
        vcT_h, vcT_l, MM, 8L * HD * MM, (long)HD * MM,
        attn, CC, (long)NN * CC, HD, nullptr, MM, HH);

    // output projection
    k_split<<<8192, 256>>>(attn, at_h, at_l, (long)BB * NN * CC);
    gemm_mma<128><<<dim3(4, 128, 1), 256, SM128>>>(
        at_h, at_l, CC, 0, 0, wpT_h, wpT_l, CC, 0, 0,
        out, CC, 0, 0, b_proj, CC, 1);
}

// round 10
// speedup vs baseline: 3.8206x; 1.5996x over previous
#include <cuda_runtime.h>
#include <cuda_bf16.h>
#include <cstdint>

#define BB 4
#define NN 4096
#define CC 512
#define HH 8
#define HD 64
#define MM 1024
#define C3 1536
#define BHZ (BB*HH)

typedef __nv_bfloat16 bf16;

__device__ bf16  g_qkv_h [BB*NN*C3];
__device__ bf16  g_qkv_l [BB*NN*C3];
__device__ bf16  g_x_h   [BB*NN*CC];
__device__ bf16  g_x_l   [BB*NN*CC];
__device__ bf16  g_wqT_h [C3*CC];
__device__ bf16  g_wqT_l [C3*CC];
__device__ bf16  g_wpT_h [CC*CC];
__device__ bf16  g_wpT_l [CC*CC];
__device__ float g_xnorm [BB*MM*CC];
__device__ float g_xr    [BB*MM*HD];
__device__ bf16  g_xr_h  [BB*MM*HD];
__device__ bf16  g_xr_l  [BB*MM*HD];
__device__ bf16  g_kc_h  [BHZ*MM*HD];
__device__ bf16  g_kc_l  [BHZ*MM*HD];
__device__ bf16  g_vc_h  [BHZ*MM*HD];
__device__ bf16  g_vc_l  [BHZ*MM*HD];
__device__ bf16  g_at_h  [BB*NN*CC];
__device__ bf16  g_at_l  [BB*NN*CC];

__device__ __forceinline__ uint32_t smem_u32(const void* p) {
    uint32_t a;
    asm("{ .reg .u64 t; cvta.to.shared.u64 t, %1; cvt.u32.u64 %0, t; }" : "=r"(a) : "l"(p));
    return a;
}
__device__ __forceinline__ void cp16(uint32_t s, const void* g) {
    asm volatile("cp.async.cg.shared.global [%0], [%1], 16;" :: "r"(s), "l"(g));
}
__device__ __forceinline__ void ldsm4(uint32_t& r0, uint32_t& r1, uint32_t& r2, uint32_t& r3, uint32_t a) {
    asm volatile("ldmatrix.sync.aligned.m8n8.x4.shared.b16 {%0,%1,%2,%3}, [%4];"
                 : "=r"(r0), "=r"(r1), "=r"(r2), "=r"(r3) : "r"(a));
}
__device__ __forceinline__ void ldsm4t(uint32_t& r0, uint32_t& r1, uint32_t& r2, uint32_t& r3, uint32_t a) {
    asm volatile("ldmatrix.sync.aligned.m8n8.x4.trans.shared.b16 {%0,%1,%2,%3}, [%4];"
                 : "=r"(r0), "=r"(r1), "=r"(r2), "=r"(r3) : "r"(a));
}
#define MMA(c, a, b) \
    asm volatile("mma.sync.aligned.m16n8k16.row.col.f32.bf16.bf16.f32 " \
        "{%0,%1,%2,%3}, {%4,%5,%6,%7}, {%8,%9}, {%0,%1,%2,%3};" \
        : "+f"((c)[0]), "+f"((c)[1]), "+f"((c)[2]), "+f"((c)[3]) \
        : "r"((a)[0]), "r"((a)[1]), "r"((a)[2]), "r"((a)[3]), "r"((b)[0]), "r"((b)[1]))

__device__ __forceinline__ uint32_t pk(float a, float b) {
    unsigned short ua = __bfloat16_as_ushort(__float2bfloat16(a));
    unsigned short ub = __bfloat16_as_ushort(__float2bfloat16(b));
    return (uint32_t)ua | ((uint32_t)ub << 16);
}
__device__ __forceinline__ float bres(float a) {
    return a - __bfloat162float(__float2bfloat16(a));
}

// ============================================================
// batched NT GEMM, split-bf16 3-MMA. Epilogue: fp32 (+bias) or split-bf16.
// ============================================================
template<int BN>
__global__ void __launch_bounds__(256, 1)
gemm_mma(const bf16* __restrict__ Ah, const bf16* __restrict__ Al,
         int lda, long Azb, long Azh,
         const bf16* __restrict__ Bh, const bf16* __restrict__ Bl,
         int ldb, long Bzb, long Bzh,
         float* __restrict__ D, bf16* __restrict__ Dhs, bf16* __restrict__ Dls,
         int ldd, long Dzb, long Dzh,
         const float* __restrict__ bias, int K, int Hdiv)
{
    constexpr int NT  = BN / 16;
    constexpr int ATB = 128 * 128;
    constexpr int BTB = BN * 128;
    constexpr int BUF = 2 * ATB + 2 * BTB;
    extern __shared__ __align__(128) char smc[];
    const uint32_t sb = smem_u32(smc);

    const int tid = threadIdx.x, lane = tid & 31, wid = tid >> 5;
    const int wm = (wid & 3) * 32, wn = (wid >> 2) * (BN / 2);
    const int z = blockIdx.z, zbq = z / Hdiv, zhq = z % Hdiv;

    const long aoff = (long)zbq * Azb + (long)zhq * Azh + (long)(blockIdx.y * 128) * lda;
    const long boff = (long)zbq * Bzb + (long)zhq * Bzh + (long)(blockIdx.x * BN) * ldb;
    const bf16* Agh = Ah + aoff;  const bf16* Agl = Al + aoff;
    const bf16* Bgh = Bh + boff;  const bf16* Bgl = Bl + boff;

    float cacc[2][NT][4];
    #pragma unroll
    for (int i = 0; i < 2; i++)
        #pragma unroll
        for (int j = 0; j < NT; j++)
            #pragma unroll
            for (int t = 0; t < 4; t++) cacc[i][j][t] = 0.f;

    auto ldA = [&](int buf, int ch) {
        const bf16* s0 = Agh + ch * 64;
        const bf16* s1 = Agl + ch * 64;
        uint32_t base = sb + buf * BUF;
        #pragma unroll
        for (int i = 0; i < 4; i++) {
            int idx = tid + i * 256;
            int r = idx >> 3, c = idx & 7;
            uint32_t d = base + r * 128 + ((c ^ (r & 7)) * 16);
            cp16(d,       s0 + (long)r * lda + c * 8);
            cp16(d + ATB, s1 + (long)r * lda + c * 8);
        }
    };
    auto ldB = [&](int buf, int ch) {
        const bf16* s0 = Bgh + ch * 64;
        const bf16* s1 = Bgl + ch * 64;
        uint32_t base = sb + buf * BUF + 2 * ATB;
        #pragma unroll
        for (int i = 0; i < (BN * 8) / 256; i++) {
            int idx = tid + i * 256;
            int r = idx >> 3, c = idx & 7;
            uint32_t d = base + r * 128 + ((c ^ (r & 7)) * 16);
            cp16(d,       s0 + (long)r * ldb + c * 8);
            cp16(d + BTB, s1 + (long)r * ldb + c * 8);
        }
    };

    const int arow = lane & 15;
    const int asel = lane >> 4;
    const int brow = ((lane >> 4) << 3) | (lane & 7);
    const int bsel = (lane >> 3) & 1;

    auto compute = [&](int buf) {
        const uint32_t ab = sb + buf * BUF;
        const uint32_t bbs = ab + 2 * ATB;
        #pragma unroll
        for (int ks = 0; ks < 4; ks++) {
            uint32_t ahf[2][4], alf[2][4], bhf[NT][2], blf[NT][2];
            #pragma unroll
            for (int mt = 0; mt < 2; mt++) {
                int row = wm + mt * 16 + arow;
                int c = ks * 2 + asel, ph = c ^ (row & 7);
                uint32_t ad = ab + row * 128 + ph * 16;
                ldsm4(ahf[mt][0], ahf[mt][1], ahf[mt][2], ahf[mt][3], ad);
                ldsm4(alf[mt][0], alf[mt][1], alf[mt][2], alf[mt][3], ad + ATB);
            }
            #pragma unroll
            for (int p = 0; p < NT / 2; p++) {
                int row = wn + p * 16 + brow;
                int c = ks * 2 + bsel, ph = c ^ (row & 7);
                uint32_t bd = bbs + row * 128 + ph * 16;
                ldsm4(bhf[2*p][0], bhf[2*p][1], bhf[2*p+1][0], bhf[2*p+1][1], bd);
                ldsm4(blf[2*p][0], blf[2*p][1], blf[2*p+1][0], blf[2*p+1][1], bd + BTB);
            }
            #pragma unroll
            for (int mt = 0; mt < 2; mt++)
                #pragma unroll
                for (int nt = 0; nt < NT; nt++) {
                    MMA(cacc[mt][nt], ahf[mt], bhf[nt]);
                    MMA(cacc[mt][nt], ahf[mt], blf[nt]);
                    MMA(cacc[mt][nt], alf[mt], bhf[nt]);
                }
        }
    };

    const int nch = K >> 6;
    ldA(0, 0); ldB(0, 0);
    asm volatile("cp.async.commit_group;" ::: "memory");
    asm volatile("cp.async.wait_group 0;" ::: "memory");
    __syncthreads();
    for (int ch = 0; ch < nch; ch++) {
        int buf = ch & 1;
        if (ch + 1 < nch) {
            ldA(buf ^ 1, ch + 1); ldB(buf ^ 1, ch + 1);
            asm volatile("cp.async.commit_group;" ::: "memory");
        }
        compute(buf);
        if (ch + 1 < nch) {
            asm volatile("cp.async.wait_group 0;" ::: "memory");
            __syncthreads();
        }
    }

    const int g = lane >> 2, tg = lane & 3;
    const long zoff = (long)zbq * Dzb + (long)zhq * Dzh;
    #pragma unroll
    for (int mt = 0; mt < 2; mt++) {
        long r0 = (long)(blockIdx.y * 128 + wm + mt * 16 + g);
        #pragma unroll
        for (int nt = 0; nt < NT; nt++) {
            int col = blockIdx.x * BN + wn + nt * 8 + tg * 2;
            float b0 = bias ? bias[col] : 0.f;
            float b1 = bias ? bias[col + 1] : 0.f;
            float v0 = cacc[mt][nt][0] + b0, v1 = cacc[mt][nt][1] + b1;
            float v2 = cacc[mt][nt][2] + b0, v3 = cacc[mt][nt][3] + b1;
            if (Dhs) {
                *(uint32_t*)(Dhs + zoff + r0 * ldd + col)       = pk(v0, v1);
                *(uint32_t*)(Dls + zoff + r0 * ldd + col)       = pk(bres(v0), bres(v1));
                *(uint32_t*)(Dhs + zoff + (r0 + 8) * ldd + col) = pk(v2, v3);
                *(uint32_t*)(Dls + zoff + (r0 + 8) * ldd + col) = pk(bres(v2), bres(v3));
            } else {
                float2 w0 = { v0, v1 }, w1 = { v2, v3 };
                *(float2*)(D + zoff + r0 * ldd + col)       = w0;
                *(float2*)(D + zoff + (r0 + 8) * ldd + col) = w1;
            }
        }
    }
}

// ============================================================
// Fused flash attention, split-bf16 HMMA. 128 Q-rows/block, KV tile 64.
// 8 warps, each owns 16 Q rows (full softmax row within warp).
// Out written as split bf16 pair (Oh, Ol).
// ============================================================
__global__ void __launch_bounds__(256, 1)
flash_mma(const bf16* __restrict__ Qh, const bf16* __restrict__ Ql,
          int qld, long qzb, long qzh,
          const bf16* __restrict__ Kh, const bf16* __restrict__ Kl,
          int kld, long kzb, long kzh,
          const bf16* __restrict__ Vh, const bf16* __restrict__ Vl,
          int vld, long vzb, long vzh,
          bf16* __restrict__ Oh, bf16* __restrict__ Ol,
          int old_, long ozb, long ozh,
          int nkv, float scale)
{
    extern __shared__ __align__(128) char smc[];
    const uint32_t sb = smem_u32(smc);   // Qh 16K | Ql 16K | stage0 32K | stage1 32K
    const int tid = threadIdx.x, lane = tid & 31, wid = tid >> 5;
    const int z = blockIdx.y, zb = z >> 3, zh = z & 7;

    const long qoff = (long)zb * qzb + (long)zh * qzh + (long)(blockIdx.x * 128) * qld;
    const bf16* qh = Qh + qoff;  const bf16* ql = Ql + qoff;
    const long koff = (long)zb * kzb + (long)zh * kzh;
    const bf16* kh = Kh + koff;  const bf16* kl = Kl + koff;
    const long voff = (long)zb * vzb + (long)zh * vzh;
    const bf16* vh = Vh + voff;  const bf16* vl = Vl + voff;

    // Q tile load (128 x 64, h+l)
    #pragma unroll
    for (int i = 0; i < 4; i++) {
        int idx = tid + i * 256;
        int r = idx >> 3, c = idx & 7;
        uint32_t d = r * 128 + ((c ^ (r & 7)) * 16);
        cp16(sb + d,         qh + (long)r * qld + c * 8);
        cp16(sb + 16384 + d, ql + (long)r * qld + c * 8);
    }
    auto ldKV = [&](int stg, int t0) {
        uint32_t base = sb + 32768u + (uint32_t)stg * 32768u;
        #pragma unroll
        for (int i = 0; i < 2; i++) {
            int idx = tid + i * 256;
            int r = idx >> 3, c = idx & 7;
            uint32_t o = r * 128 + ((c ^ (r & 7)) * 16);
            long gr = (long)(t0 + r);
            cp16(base + o,         kh + gr * kld + c * 8);
            cp16(base + 8192 + o,  kl + gr * kld + c * 8);
            cp16(base + 16384 + o, vh + gr * vld + c * 8);
            cp16(base + 24576 + o, vl + gr * vld + c * 8);
        }
    };
    ldKV(0, 0);
    asm volatile("cp.async.commit_group;" ::: "memory");

    float oacc[8][4];
    #pragma unroll
    for (int j = 0; j < 8; j++) { oacc[j][0]=oacc[j][1]=oacc[j][2]=oacc[j][3]=0.f; }
    float m0 = -1e30f, m1 = -1e30f, l0 = 0.f, l1 = 0.f;

    const int ntile = nkv >> 6;
    for (int t = 0; t < ntile; t++) {
        if (t + 1 < ntile) {
            ldKV((t + 1) & 1, (t + 1) << 6);
            asm volatile("cp.async.commit_group;" ::: "memory");
            asm volatile("cp.async.wait_group 1;" ::: "memory");
        } else {
            asm volatile("cp.async.wait_group 0;" ::: "memory");
        }
        __syncthreads();

        const uint32_t kb = sb + 32768u + (uint32_t)(t & 1) * 32768u;
        // ---- S = Q @ K^T (split 3-MMA) ----
        float s[8][4];
        #pragma unroll
        for (int nt = 0; nt < 8; nt++) { s[nt][0]=s[nt][1]=s[nt][2]=s[nt][3]=0.f; }
        #pragma unroll
        for (int ks = 0; ks < 4; ks++) {
            uint32_t aH[4], aL[4];
            {
                int row = wid * 16 + (lane & 15);
                int c = ks * 2 + (lane >> 4), ph = c ^ (row & 7);
                uint32_t ad = sb + row * 128 + ph * 16;
                ldsm4(aH[0], aH[1], aH[2], aH[3], ad);
                ldsm4(aL[0], aL[1], aL[2], aL[3], ad + 16384);
            }
            #pragma unroll
            for (int p = 0; p < 4; p++) {
                int row = p * 16 + (((lane >> 4) << 3) | (lane & 7));
                int c = ks * 2 + ((lane >> 3) & 1), ph = c ^ (row & 7);
                uint32_t bd = kb + row * 128 + ph * 16;
                uint32_t bh[4], bl[4];
                ldsm4(bh[0], bh[1], bh[2], bh[3], bd);
                ldsm4(bl[0], bl[1], bl[2], bl[3], bd + 8192);
                MMA(s[2*p],   aH, bh);     MMA(s[2*p],   aH, bl);     MMA(s[2*p],   aL, bh);
                MMA(s[2*p+1], aH, bh + 2); MMA(s[2*p+1], aH, bl + 2); MMA(s[2*p+1], aL, bh + 2);
            }
        }
        // ---- online softmax (rows g=lane>>2 and g+8; 4 threads/row) ----
        float mx0 = -1e30f, mx1 = -1e30f;
        #pragma unroll
        for (int nt = 0; nt < 8; nt++) {
            s[nt][0] *= scale; s[nt][1] *= scale; s[nt][2] *= scale; s[nt][3] *= scale;
            mx0 = fmaxf(mx0, fmaxf(s[nt][0], s[nt][1]));
            mx1 = fmaxf(mx1, fmaxf(s[nt][2], s[nt][3]));
        }
        mx0 = fmaxf(mx0, __shfl_xor_sync(0xffffffffu, mx0, 1));
        mx0 = fmaxf(mx0, __shfl_xor_sync(0xffffffffu, mx0, 2));
        mx1 = fmaxf(mx1, __shfl_xor_sync(0xffffffffu, mx1, 1));
        mx1 = fmaxf(mx1, __shfl_xor_sync(0xffffffffu, mx1, 2));
        float mn0 = fmaxf(m0, mx0), mn1 = fmaxf(m1, mx1);
        float al0 = __expf(m0 - mn0), al1 = __expf(m1 - mn1);
        m0 = mn0; m1 = mn1;
        float rs0 = 0.f, rs1 = 0.f;
        #pragma unroll
        for (int nt = 0; nt < 8; nt++) {
            s[nt][0] = __expf(s[nt][0] - mn0); s[nt][1] = __expf(s[nt][1] - mn0);
            s[nt][2] = __expf(s[nt][2] - mn1); s[nt][3] = __expf(s[nt][3] - mn1);
            rs0 += s[nt][0] + s[nt][1];
            rs1 += s[nt][2] + s[nt][3];
        }
        rs0 += __shfl_xor_sync(0xffffffffu, rs0, 1);
        rs0 += __shfl_xor_sync(0xffffffffu, rs0, 2);
        rs1 += __shfl_xor_sync(0xffffffffu, rs1, 1);
        rs1 += __shfl_xor_sync(0xffffffffu, rs1, 2);
        l0 = l0 * al0 + rs0;
        l1 = l1 * al1 + rs1;
        #pragma unroll
        for (int j = 0; j < 8; j++) {
            oacc[j][0] *= al0; oacc[j][1] *= al0;
            oacc[j][2] *= al1; oacc[j][3] *= al1;
        }
        // ---- O += P @ V (P fragments from registers, V via ldmatrix.trans) ----
        #pragma unroll
        for (int ks = 0; ks < 4; ks++) {
            uint32_t aH[4] = { pk(s[2*ks][0],   s[2*ks][1]),   pk(s[2*ks][2],   s[2*ks][3]),
                               pk(s[2*ks+1][0], s[2*ks+1][1]), pk(s[2*ks+1][2], s[2*ks+1][3]) };
            uint32_t aL[4] = { pk(bres(s[2*ks][0]),   bres(s[2*ks][1])),
                               pk(bres(s[2*ks][2]),   bres(s[2*ks][3])),
                               pk(bres(s[2*ks+1][0]), bres(s[2*ks+1][1])),
                               pk(bres(s[2*ks+1][2]), bres(s[2*ks+1][3])) };
            #pragma unroll
            for (int p = 0; p < 4; p++) {
                int row = ks * 16 + ((lane >> 3) & 1) * 8 + (lane & 7);
                int c = p * 2 + (lane >> 4), ph = c ^ (row & 7);
                uint32_t vd = kb + 16384 + row * 128 + ph * 16;
                uint32_t bvh[4], bvl[4];
                ldsm4t(bvh[0], bvh[1], bvh[2], bvh[3], vd);
                ldsm4t(bvl[0], bvl[1], bvl[2], bvl[3], vd + 8192);
                MMA(oacc[2*p],   aH, bvh);     MMA(oacc[2*p],   aH, bvl);     MMA(oacc[2*p],   aL, bvh);
                MMA(oacc[2*p+1], aH, bvh + 2); MMA(oacc[2*p+1], aH, bvl + 2); MMA(oacc[2*p+1], aL, bvh + 2);
            }
        }
        __syncthreads();
    }

    // ---- epilogue: O / l, write split bf16 ----
    float il0 = 1.f / l0, il1 = 1.f / l1;
    const long obase = (long)zb * ozb + (long)zh * ozh;
    const long r0 = (long)(blockIdx.x * 128 + wid * 16 + (lane >> 2));
    #pragma unroll
    for (int j = 0; j < 8; j++) {
        int col = j * 8 + (lane & 3) * 2;
        float v0 = oacc[j][0] * il0, v1 = oacc[j][1] * il0;
        float v2 = oacc[j][2] * il1, v3 = oacc[j][3] * il1;
        *(uint32_t*)(Oh + obase + r0 * old_ + col)       = pk(v0, v1);
        *(uint32_t*)(Ol + obase + r0 * old_ + col)       = pk(bres(v0), bres(v1));
        *(uint32_t*)(Oh + obase + (r0 + 8) * old_ + col) = pk(v2, v3);
        *(uint32_t*)(Ol + obase + (r0 + 8) * old_ + col) = pk(bres(v2), bres(v3));
    }
}

__global__ void k_split(const float* __restrict__ in, bf16* __restrict__ oh,
                        bf16* __restrict__ ol, long n) {
    long idx = ((long)blockIdx.x * blockDim.x + threadIdx.x) * 4;
    if (idx >= n) return;
    float4 f = *(const float4*)(in + idx);
    uint2 uh; uh.x = pk(f.x, f.y); uh.y = pk(f.z, f.w);
    uint2 ul; ul.x = pk(bres(f.x), bres(f.y)); ul.y = pk(bres(f.z), bres(f.w));
    *(uint2*)(oh + idx) = uh;
    *(uint2*)(ol + idx) = ul;
}

__global__ void k_trsplit(const float* __restrict__ in, int ldin,
                          bf16* __restrict__ oh, bf16* __restrict__ ol, int ldout) {
    __shared__ float t[32][33];
    const int r0 = blockIdx.x * 32, c0 = blockIdx.y * 32;
    const int tx = threadIdx.x & 31, ty = threadIdx.x >> 5;
    #pragma unroll
    for (int i = 0; i < 4; i++) {
        int r = ty + i * 8;
        t[r][tx] = in[(long)(r0 + r) * ldin + c0 + tx];
    }
    __syncthreads();
    #pragma unroll
    for (int i = 0; i < 4; i++) {
        int oc = ty + i * 8;
        float f = t[tx][oc];
        long o = (long)(c0 + oc) * ldout + r0 + tx;
        oh[o] = __float2bfloat16(f);
        ol[o] = __float2bfloat16(bres(f));
    }
}

__global__ void gemm64(const float* __restrict__ A, const float* __restrict__ B,
                       const float* __restrict__ bias, float* __restrict__ C,
                       int Md, int Nd, int Kd) {
    __shared__ float As[16][68];
    __shared__ float Bs[16][68];
    const int tx = threadIdx.x & 15;
    const int ty = threadIdx.x >> 4;
    const int rowBase = blockIdx.y * 64;
    const int colBase = blockIdx.x * 64;
    float acc[4][4] = {};
    for (int k0 = 0; k0 < Kd; k0 += 16) {
        for (int t = threadIdx.x; t < 1024; t += 256) {
            int m = t >> 4, kk = t & 15;
            As[kk][m] = A[(long)(rowBase + m) * Kd + k0 + kk];
        }
        for (int t = threadIdx.x; t < 1024; t += 256) {
            int kk = t >> 6, n = t & 63;
            Bs[kk][n] = B[(long)(k0 + kk) * Nd + colBase + n];
        }
        __syncthreads();
        #pragma unroll
        for (int kk = 0; kk < 16; kk++) {
            float a[4], b[4];
            #pragma unroll
            for (int i = 0; i < 4; i++) a[i] = As[kk][ty * 4 + i];
            #pragma unroll
            for (int j = 0; j < 4; j++) b[j] = Bs[kk][tx * 4 + j];
            #pragma unroll
            for (int i = 0; i < 4; i++)
                #pragma unroll
                for (int j = 0; j < 4; j++) acc[i][j] += a[i] * b[j];
        }
        __syncthreads();
    }
    #pragma unroll
    for (int i = 0; i < 4; i++) {
        long r = rowBase + ty * 4 + i;
        #pragma unroll
        for (int j = 0; j < 4; j++) {
            int c = colBase + tx * 4 + j;
            float v = acc[i][j];
            if (bias) v += bias[c];
            C[r * Nd + c] = v;
        }
    }
}

__global__ void sr_conv_ln(const float* __restrict__ x, const float* __restrict__ wc,
                           const float* __restrict__ bc, const float* __restrict__ gam,
                           const float* __restrict__ bet, float* __restrict__ out) {
    const int bm = blockIdx.x;
    const int b = bm >> 10, m = bm & 1023;
    const int oi = m >> 5, oj = m & 31;
    const long base = ((long)b * NN + oi * 128 + oj * 2) * CC;
    __shared__ float red[4];
    const int tid = threadIdx.x;
    float y[4];
    float loc = 0.f;
    #pragma unroll
    for (int cc = 0; cc < 4; cc++) {
        int c = tid + cc * 128;
        float v = x[base + c]           * wc[c * 4 + 0]
                + x[base + CC + c]      * wc[c * 4 + 1]
                + x[base + 64 * CC + c] * wc[c * 4 + 2]
                + x[base + 65 * CC + c] * wc[c * 4 + 3]
                + bc[c];
        y[cc] = v; loc += v;
    }
    #pragma unroll
    for (int o = 16; o >= 1; o >>= 1) loc += __shfl_xor_sync(0xffffffffu, loc, o);
    if ((tid & 31) == 0) red[tid >> 5] = loc;
    __syncthreads();
    float mu = (red[0] + red[1] + red[2] + red[3]) * (1.f / 512.f);
    float lv = 0.f;
    #pragma unroll
    for (int cc = 0; cc < 4; cc++) { float d = y[cc] - mu; lv += d * d; }
    #pragma unroll
    for (int o = 16; o >= 1; o >>= 1) lv += __shfl_xor_sync(0xffffffffu, lv, o);
    __syncthreads();
    if ((tid & 31) == 0) red[tid >> 5] = lv;
    __syncthreads();
    float var = (red[0] + red[1] + red[2] + red[3]) * (1.f / 512.f);
    float inv = rsqrtf(var + 1e-5f);
    long ob = ((long)b * MM + m) * CC;
    #pragma unroll
    for (int cc = 0; cc < 4; cc++) {
        int c = tid + cc * 128;
        out[ob + c] = (y[cc] - mu) * inv * gam[c] + bet[c];
    }
}

extern "C" void kernel_launch(void* const* d_in, const int* in_sizes, int n_in,
                              void* d_out, int out_size) {
    const float* x         = (const float*)d_in[0];
    const float* w_qkv     = (const float*)d_in[1];
    const float* w_proj    = (const float*)d_in[2];
    const float* b_proj    = (const float*)d_in[3];
    const float* w_sr_conv = (const float*)d_in[4];
    const float* b_sr_conv = (const float*)d_in[5];
    const float* gam       = (const float*)d_in[6];
    const float* bet       = (const float*)d_in[7];
    const float* w_sr_lin  = (const float*)d_in[8];
    const float* b_sr_lin  = (const float*)d_in[9];
    float* out = (float*)d_out;

    float *xnorm, *xr;
    bf16 *qkv_h,*qkv_l,*x_h,*x_l,*wqT_h,*wqT_l,*wpT_h,*wpT_l;
    bf16 *xr_h,*xr_l,*kc_h,*kc_l,*vc_h,*vc_l,*at_h,*at_l;
    cudaGetSymbolAddress((void**)&qkv_h, g_qkv_h);
    cudaGetSymbolAddress((void**)&qkv_l, g_qkv_l);
    cudaGetSymbolAddress((void**)&x_h,   g_x_h);
    cudaGetSymbolAddress((void**)&x_l,   g_x_l);
    cudaGetSymbolAddress((void**)&wqT_h, g_wqT_h);
    cudaGetSymbolAddress((void**)&wqT_l, g_wqT_l);
    cudaGetSymbolAddress((void**)&wpT_h, g_wpT_h);
    cudaGetSymbolAddress((void**)&wpT_l, g_wpT_l);
    cudaGetSymbolAddress((void**)&xnorm, g_xnorm);
    cudaGetSymbolAddress((void**)&xr,    g_xr);
    cudaGetSymbolAddress((void**)&xr_h,  g_xr_h);
    cudaGetSymbolAddress((void**)&xr_l,  g_xr_l);
    cudaGetSymbolAddress((void**)&kc_h,  g_kc_h);
    cudaGetSymbolAddress((void**)&kc_l,  g_kc_l);
    cudaGetSymbolAddress((void**)&vc_h,  g_vc_h);
    cudaGetSymbolAddress((void**)&vc_l,  g_vc_l);
    cudaGetSymbolAddress((void**)&at_h,  g_at_h);
    cudaGetSymbolAddress((void**)&at_l,  g_at_l);

    const int SM128 = 2 * (2 * 128 * 128 + 2 * 128 * 128);  // 131072
    const int FSM   = 96 * 1024;                             //  98304
    cudaFuncSetAttribute((const void*)gemm_mma<128>,
                         cudaFuncAttributeMaxDynamicSharedMemorySize, SM128);
    cudaFuncSetAttribute((const void*)flash_mma,
                         cudaFuncAttributeMaxDynamicSharedMemorySize, FSM);

    const long NC3  = (long)NN * C3;
    const long KCZB = (long)HH * MM * HD;  // batch stride of kc/vc
    const long KCZH = (long)MM * HD;

    // input/weight conversions
    k_split<<<8192, 256>>>(x, x_h, x_l, (long)BB * NN * CC);
    k_trsplit<<<dim3(16, 48), 256>>>(w_qkv, C3, wqT_h, wqT_l, CC);
    k_trsplit<<<dim3(16, 16), 256>>>(w_proj, CC, wpT_h, wpT_l, CC);

    // QKV projection -> split bf16 directly
    gemm_mma<128><<<dim3(12, 128, 1), 256, SM128>>>(
        x_h, x_l, CC, 0, 0,  wqT_h, wqT_l, CC, 0, 0,
        nullptr, qkv_h, qkv_l, C3, 0, 0, nullptr, CC, 1);

    // SR branch
    sr_conv_ln<<<BB * MM, 128>>>(x, w_sr_conv, b_sr_conv, gam, bet, xnorm);
    gemm64<<<dim3(1, 64), 256>>>(xnorm, w_sr_lin, b_sr_lin, xr, BB * MM, HD, CC);
    k_split<<<256, 256>>>(xr, xr_h, xr_l, (long)BB * MM * HD);

    // flash 1: kc = softmax(x_ k^T) k     (K = V = k slice)
    flash_mma<<<dim3(8, 32), 256, FSM>>>(
        xr_h, xr_l, HD, (long)MM * HD, 0L,
        qkv_h + CC, qkv_l + CC, C3, NC3, (long)HD,
        qkv_h + CC, qkv_l + CC, C3, NC3, (long)HD,
        kc_h, kc_l, HD, KCZB, KCZH, NN, 1.0f);

    // flash 2: vc = softmax(x_ v^T) v
    flash_mma<<<dim3(8, 32), 256, FSM>>>(
        xr_h, xr_l, HD, (long)MM * HD, 0L,
        qkv_h + 2 * CC, qkv_l + 2 * CC, C3, NC3, (long)HD,
        qkv_h + 2 * CC, qkv_l + 2 * CC, C3, NC3, (long)HD,
        vc_h, vc_l, HD, KCZB, KCZH, NN, 1.0f);

    // flash 3: attn = softmax(q kc^T / 8) vc -> [b, n, h, d] split
    flash_mma<<<dim3(32, 32), 256, FSM>>>(
        qkv_h, qkv_l, C3, NC3, (long)HD,
        kc_h, kc_l, HD, KCZB, KCZH,
        vc_h, vc_l, HD, KCZB, KCZH,
        at_h, at_l, CC, (long)NN * CC, (long)HD, MM, 0.125f);

    // output projection (fp32 out + bias)
    gemm_mma<128><<<dim3(4, 128, 1), 256, SM128>>>(
        at_h, at_l, CC, 0, 0, wpT_h, wpT_l, CC, 0, 0,
        out, nullptr, nullptr, CC, 0, 0, b_proj, CC, 1);
}

// round 11
// speedup vs baseline: 3.9033x; 1.0217x over previous
#include <cuda_runtime.h>
#include <cuda_bf16.h>
#include <cstdint>

#define BB 4
#define NN 4096
#define CC 512
#define HH 8
#define HD 64
#define MM 1024
#define C3 1536
#define BHZ (BB*HH)

typedef __nv_bfloat16 bf16;

__device__ bf16  g_qkv_h [BB*NN*C3];
__device__ bf16  g_qkv_l [BB*NN*C3];
__device__ bf16  g_x_h   [BB*NN*CC];
__device__ bf16  g_x_l   [BB*NN*CC];
__device__ bf16  g_wqT_h [C3*CC];
__device__ bf16  g_wqT_l [C3*CC];
__device__ bf16  g_wpT_h [CC*CC];
__device__ bf16  g_wpT_l [CC*CC];
__device__ float g_xnorm [BB*MM*CC];
__device__ float g_xr    [BB*MM*HD];
__device__ bf16  g_xr_h  [BB*MM*HD];
__device__ bf16  g_xr_l  [BB*MM*HD];
__device__ bf16  g_kc_h  [BHZ*MM*HD];
__device__ bf16  g_kc_l  [BHZ*MM*HD];
__device__ bf16  g_vc_h  [BHZ*MM*HD];
__device__ bf16  g_vc_l  [BHZ*MM*HD];
__device__ bf16  g_at_h  [BB*NN*CC];
__device__ bf16  g_at_l  [BB*NN*CC];

__device__ __forceinline__ uint32_t smem_u32(const void* p) {
    uint32_t a;
    asm("{ .reg .u64 t; cvta.to.shared.u64 t, %1; cvt.u32.u64 %0, t; }" : "=r"(a) : "l"(p));
    return a;
}
__device__ __forceinline__ void cp16(uint32_t s, const void* g) {
    asm volatile("cp.async.cg.shared.global [%0], [%1], 16;" :: "r"(s), "l"(g));
}
__device__ __forceinline__ void ldsm4(uint32_t& r0, uint32_t& r1, uint32_t& r2, uint32_t& r3, uint32_t a) {
    asm volatile("ldmatrix.sync.aligned.m8n8.x4.shared.b16 {%0,%1,%2,%3}, [%4];"
                 : "=r"(r0), "=r"(r1), "=r"(r2), "=r"(r3) : "r"(a));
}
__device__ __forceinline__ void ldsm4t(uint32_t& r0, uint32_t& r1, uint32_t& r2, uint32_t& r3, uint32_t a) {
    asm volatile("ldmatrix.sync.aligned.m8n8.x4.trans.shared.b16 {%0,%1,%2,%3}, [%4];"
                 : "=r"(r0), "=r"(r1), "=r"(r2), "=r"(r3) : "r"(a));
}
#define MMA(c, a, b) \
    asm volatile("mma.sync.aligned.m16n8k16.row.col.f32.bf16.bf16.f32 " \
        "{%0,%1,%2,%3}, {%4,%5,%6,%7}, {%8,%9}, {%0,%1,%2,%3};" \
        : "+f"((c)[0]), "+f"((c)[1]), "+f"((c)[2]), "+f"((c)[3]) \
        : "r"((a)[0]), "r"((a)[1]), "r"((a)[2]), "r"((a)[3]), "r"((b)[0]), "r"((b)[1]))

__device__ __forceinline__ uint32_t pk(float a, float b) {
    unsigned short ua = __bfloat16_as_ushort(__float2bfloat16(a));
    unsigned short ub = __bfloat16_as_ushort(__float2bfloat16(b));
    return (uint32_t)ua | ((uint32_t)ub << 16);
}
__device__ __forceinline__ float bres(float a) {
    return a - __bfloat162float(__float2bfloat16(a));
}

// ============================================================
// batched NT GEMM, split-bf16 3-MMA. Epilogue: fp32 (+bias) or split-bf16.
// ============================================================
template<int BN>
__global__ void __launch_bounds__(256, 1)
gemm_mma(const bf16* __restrict__ Ah, const bf16* __restrict__ Al,
         int lda, long Azb, long Azh,
         const bf16* __restrict__ Bh, const bf16* __restrict__ Bl,
         int ldb, long Bzb, long Bzh,
         float* __restrict__ D, bf16* __restrict__ Dhs, bf16* __restrict__ Dls,
         int ldd, long Dzb, long Dzh,
         const float* __restrict__ bias, int K, int Hdiv)
{
    constexpr int NT  = BN / 16;
    constexpr int ATB = 128 * 128;
    constexpr int BTB = BN * 128;
    constexpr int BUF = 2 * ATB + 2 * BTB;
    extern __shared__ __align__(128) char smc[];
    const uint32_t sb = smem_u32(smc);

    const int tid = threadIdx.x, lane = tid & 31, wid = tid >> 5;
    const int wm = (wid & 3) * 32, wn = (wid >> 2) * (BN / 2);
    const int z = blockIdx.z, zbq = z / Hdiv, zhq = z % Hdiv;

    const long aoff = (long)zbq * Azb + (long)zhq * Azh + (long)(blockIdx.y * 128) * lda;
    const long boff = (long)zbq * Bzb + (long)zhq * Bzh + (long)(blockIdx.x * BN) * ldb;
    const bf16* Agh = Ah + aoff;  const bf16* Agl = Al + aoff;
    const bf16* Bgh = Bh + boff;  const bf16* Bgl = Bl + boff;

    float cacc[2][NT][4];
    #pragma unroll
    for (int i = 0; i < 2; i++)
        #pragma unroll
        for (int j = 0; j < NT; j++)
            #pragma unroll
            for (int t = 0; t < 4; t++) cacc[i][j][t] = 0.f;

    auto ldA = [&](int buf, int ch) {
        const bf16* s0 = Agh + ch * 64;
        const bf16* s1 = Agl + ch * 64;
        uint32_t base = sb + buf * BUF;
        #pragma unroll
        for (int i = 0; i < 4; i++) {
            int idx = tid + i * 256;
            int r = idx >> 3, c = idx & 7;
            uint32_t d = base + r * 128 + ((c ^ (r & 7)) * 16);
            cp16(d,       s0 + (long)r * lda + c * 8);
            cp16(d + ATB, s1 + (long)r * lda + c * 8);
        }
    };
    auto ldB = [&](int buf, int ch) {
        const bf16* s0 = Bgh + ch * 64;
        const bf16* s1 = Bgl + ch * 64;
        uint32_t base = sb + buf * BUF + 2 * ATB;
        #pragma unroll
        for (int i = 0; i < (BN * 8) / 256; i++) {
            int idx = tid + i * 256;
            int r = idx >> 3, c = idx & 7;
            uint32_t d = base + r * 128 + ((c ^ (r & 7)) * 16);
            cp16(d,       s0 + (long)r * ldb + c * 8);
            cp16(d + BTB, s1 + (long)r * ldb + c * 8);
        }
    };

    const int arow = lane & 15;
    const int asel = lane >> 4;
    const int brow = ((lane >> 4) << 3) | (lane & 7);
    const int bsel = (lane >> 3) & 1;

    auto compute = [&](int buf) {
        const uint32_t ab = sb + buf * BUF;
        const uint32_t bbs = ab + 2 * ATB;
        #pragma unroll
        for (int ks = 0; ks < 4; ks++) {
            uint32_t ahf[2][4], alf[2][4], bhf[NT][2], blf[NT][2];
            #pragma unroll
            for (int mt = 0; mt < 2; mt++) {
                int row = wm + mt * 16 + arow;
                int c = ks * 2 + asel, ph = c ^ (row & 7);
                uint32_t ad = ab + row * 128 + ph * 16;
                ldsm4(ahf[mt][0], ahf[mt][1], ahf[mt][2], ahf[mt][3], ad);
                ldsm4(alf[mt][0], alf[mt][1], alf[mt][2], alf[mt][3], ad + ATB);
            }
            #pragma unroll
            for (int p = 0; p < NT / 2; p++) {
                int row = wn + p * 16 + brow;
                int c = ks * 2 + bsel, ph = c ^ (row & 7);
                uint32_t bd = bbs + row * 128 + ph * 16;
                ldsm4(bhf[2*p][0], bhf[2*p][1], bhf[2*p+1][0], bhf[2*p+1][1], bd);
                ldsm4(blf[2*p][0], blf[2*p][1], blf[2*p+1][0], blf[2*p+1][1], bd + BTB);
            }
            #pragma unroll
            for (int mt = 0; mt < 2; mt++)
                #pragma unroll
                for (int nt = 0; nt < NT; nt++) {
                    MMA(cacc[mt][nt], ahf[mt], bhf[nt]);
                    MMA(cacc[mt][nt], ahf[mt], blf[nt]);
                    MMA(cacc[mt][nt], alf[mt], bhf[nt]);
                }
        }
    };

    const int nch = K >> 6;
    ldA(0, 0); ldB(0, 0);
    asm volatile("cp.async.commit_group;" ::: "memory");
    asm volatile("cp.async.wait_group 0;" ::: "memory");
    __syncthreads();
    for (int ch = 0; ch < nch; ch++) {
        int buf = ch & 1;
        if (ch + 1 < nch) {
            ldA(buf ^ 1, ch + 1); ldB(buf ^ 1, ch + 1);
            asm volatile("cp.async.commit_group;" ::: "memory");
        }
        compute(buf);
        if (ch + 1 < nch) {
            asm volatile("cp.async.wait_group 0;" ::: "memory");
            __syncthreads();
        }
    }

    const int g = lane >> 2, tg = lane & 3;
    const long zoff = (long)zbq * Dzb + (long)zhq * Dzh;
    #pragma unroll
    for (int mt = 0; mt < 2; mt++) {
        long r0 = (long)(blockIdx.y * 128 + wm + mt * 16 + g);
        #pragma unroll
        for (int nt = 0; nt < NT; nt++) {
            int col = blockIdx.x * BN + wn + nt * 8 + tg * 2;
            float b0 = bias ? bias[col] : 0.f;
            float b1 = bias ? bias[col + 1] : 0.f;
            float v0 = cacc[mt][nt][0] + b0, v1 = cacc[mt][nt][1] + b1;
            float v2 = cacc[mt][nt][2] + b0, v3 = cacc[mt][nt][3] + b1;
            if (Dhs) {
                *(uint32_t*)(Dhs + zoff + r0 * ldd + col)       = pk(v0, v1);
                *(uint32_t*)(Dls + zoff + r0 * ldd + col)       = pk(bres(v0), bres(v1));
                *(uint32_t*)(Dhs + zoff + (r0 + 8) * ldd + col) = pk(v2, v3);
                *(uint32_t*)(Dls + zoff + (r0 + 8) * ldd + col) = pk(bres(v2), bres(v3));
            } else {
                float2 w0 = { v0, v1 }, w1 = { v2, v3 };
                *(float2*)(D + zoff + r0 * ldd + col)       = w0;
                *(float2*)(D + zoff + (r0 + 8) * ldd + col) = w1;
            }
        }
    }
}

// ============================================================
// Fused flash attention, split-bf16 HMMA. 128 Q-rows/block, KV tile 64.
// KVSAME: V aliases K (pooling attention) -> half the smem + loads.
// gridDim.z selects K-slice offset (z*kzz) and output 0/1.
// Q fragments preloaded into registers (loop-invariant).
// ============================================================
template<bool KVSAME>
__global__ void __launch_bounds__(256, 1)
flash_mma(const bf16* __restrict__ Qh, const bf16* __restrict__ Ql,
          int qld, long qzb, long qzh,
          const bf16* __restrict__ Kh, const bf16* __restrict__ Kl,
          int kld, long kzb, long kzh, long kzz,
          const bf16* __restrict__ Vh, const bf16* __restrict__ Vl,
          int vld, long vzb, long vzh,
          bf16* __restrict__ Oh0, bf16* __restrict__ Ol0,
          bf16* __restrict__ Oh1, bf16* __restrict__ Ol1,
          int old_, long ozb, long ozh,
          int nkv, float scale)
{
    constexpr uint32_t STG = KVSAME ? 16384u : 32768u;
    extern __shared__ __align__(128) char smc[];
    const uint32_t sb = smem_u32(smc);   // Qh 16K | Ql 16K | stages
    const int tid = threadIdx.x, lane = tid & 31, wid = tid >> 5;
    const int z = blockIdx.y, zb = z >> 3, zh = z & 7;
    const int zz = blockIdx.z;

    const long qoff = (long)zb * qzb + (long)zh * qzh + (long)(blockIdx.x * 128) * qld;
    const bf16* qh = Qh + qoff;  const bf16* ql = Ql + qoff;
    const long koff = (long)zb * kzb + (long)zh * kzh + (long)zz * kzz;
    const bf16* kh = Kh + koff;  const bf16* kl = Kl + koff;
    const bf16* vh; const bf16* vl;
    if (KVSAME) { vh = kh; vl = kl; }
    else {
        long voff = (long)zb * vzb + (long)zh * vzh;
        vh = Vh + voff; vl = Vl + voff;
    }
    bf16* Oh = zz ? Oh1 : Oh0;
    bf16* Ol = zz ? Ol1 : Ol0;

    // Q tile load (128 x 64, h+l)
    #pragma unroll
    for (int i = 0; i < 4; i++) {
        int idx = tid + i * 256;
        int r = idx >> 3, c = idx & 7;
        uint32_t d = r * 128 + ((c ^ (r & 7)) * 16);
        cp16(sb + d,         qh + (long)r * qld + c * 8);
        cp16(sb + 16384 + d, ql + (long)r * qld + c * 8);
    }
    auto ldKV = [&](int stg, int t0) {
        uint32_t base = sb + 32768u + (uint32_t)stg * STG;
        #pragma unroll
        for (int i = 0; i < 2; i++) {
            int idx = tid + i * 256;
            int r = idx >> 3, c = idx & 7;
            uint32_t o = r * 128 + ((c ^ (r & 7)) * 16);
            long gr = (long)(t0 + r);
            cp16(base + o,        kh + gr * kld + c * 8);
            cp16(base + 8192 + o, kl + gr * kld + c * 8);
            if (!KVSAME) {
                cp16(base + 16384 + o, vh + gr * vld + c * 8);
                cp16(base + 24576 + o, vl + gr * vld + c * 8);
            }
        }
    };
    ldKV(0, 0);
    asm volatile("cp.async.commit_group;" ::: "memory");
    asm volatile("cp.async.wait_group 0;" ::: "memory");
    __syncthreads();

    // preload Q fragments (loop-invariant)
    uint32_t aH[4][4], aL[4][4];
    #pragma unroll
    for (int ks = 0; ks < 4; ks++) {
        int row = wid * 16 + (lane & 15);
        int c = ks * 2 + (lane >> 4), ph = c ^ (row & 7);
        uint32_t ad = sb + row * 128 + ph * 16;
        ldsm4(aH[ks][0], aH[ks][1], aH[ks][2], aH[ks][3], ad);
        ldsm4(aL[ks][0], aL[ks][1], aL[ks][2], aL[ks][3], ad + 16384);
    }

    float oacc[8][4];
    #pragma unroll
    for (int j = 0; j < 8; j++) { oacc[j][0]=oacc[j][1]=oacc[j][2]=oacc[j][3]=0.f; }
    float m0 = -1e30f, m1 = -1e30f, l0 = 0.f, l1 = 0.f;

    const int ntile = nkv >> 6;
    for (int t = 0; t < ntile; t++) {
        if (t + 1 < ntile) {
            ldKV((t + 1) & 1, (t + 1) << 6);
            asm volatile("cp.async.commit_group;" ::: "memory");
            asm volatile("cp.async.wait_group 1;" ::: "memory");
        } else {
            asm volatile("cp.async.wait_group 0;" ::: "memory");
        }
        __syncthreads();

        const uint32_t kb = sb + 32768u + (uint32_t)(t & 1) * STG;
        // ---- S = Q @ K^T (split 3-MMA, Q frags from regs) ----
        float s[8][4];
        #pragma unroll
        for (int nt = 0; nt < 8; nt++) { s[nt][0]=s[nt][1]=s[nt][2]=s[nt][3]=0.f; }
        #pragma unroll
        for (int ks = 0; ks < 4; ks++) {
            #pragma unroll
            for (int p = 0; p < 4; p++) {
                int row = p * 16 + (((lane >> 4) << 3) | (lane & 7));
                int c = ks * 2 + ((lane >> 3) & 1), ph = c ^ (row & 7);
                uint32_t bd = kb + row * 128 + ph * 16;
                uint32_t bh[4], bl[4];
                ldsm4(bh[0], bh[1], bh[2], bh[3], bd);
                ldsm4(bl[0], bl[1], bl[2], bl[3], bd + 8192);
                MMA(s[2*p],   aH[ks], bh);     MMA(s[2*p],   aH[ks], bl);     MMA(s[2*p],   aL[ks], bh);
                MMA(s[2*p+1], aH[ks], bh + 2); MMA(s[2*p+1], aH[ks], bl + 2); MMA(s[2*p+1], aL[ks], bh + 2);
            }
        }
        // ---- online softmax ----
        float mx0 = -1e30f, mx1 = -1e30f;
        #pragma unroll
        for (int nt = 0; nt < 8; nt++) {
            s[nt][0] *= scale; s[nt][1] *= scale; s[nt][2] *= scale; s[nt][3] *= scale;
            mx0 = fmaxf(mx0, fmaxf(s[nt][0], s[nt][1]));
            mx1 = fmaxf(mx1, fmaxf(s[nt][2], s[nt][3]));
        }
        mx0 = fmaxf(mx0, __shfl_xor_sync(0xffffffffu, mx0, 1));
        mx0 = fmaxf(mx0, __shfl_xor_sync(0xffffffffu, mx0, 2));
        mx1 = fmaxf(mx1, __shfl_xor_sync(0xffffffffu, mx1, 1));
        mx1 = fmaxf(mx1, __shfl_xor_sync(0xffffffffu, mx1, 2));
        float mn0 = fmaxf(m0, mx0), mn1 = fmaxf(m1, mx1);
        float al0 = __expf(m0 - mn0), al1 = __expf(m1 - mn1);
        m0 = mn0; m1 = mn1;
        float rs0 = 0.f, rs1 = 0.f;
        #pragma unroll
        for (int nt = 0; nt < 8; nt++) {
            s[nt][0] = __expf(s[nt][0] - mn0); s[nt][1] = __expf(s[nt][1] - mn0);
            s[nt][2] = __expf(s[nt][2] - mn1); s[nt][3] = __expf(s[nt][3] - mn1);
            rs0 += s[nt][0] + s[nt][1];
            rs1 += s[nt][2] + s[nt][3];
        }
        rs0 += __shfl_xor_sync(0xffffffffu, rs0, 1);
        rs0 += __shfl_xor_sync(0xffffffffu, rs0, 2);
        rs1 += __shfl_xor_sync(0xffffffffu, rs1, 1);
        rs1 += __shfl_xor_sync(0xffffffffu, rs1, 2);
        l0 = l0 * al0 + rs0;
        l1 = l1 * al1 + rs1;
        #pragma unroll
        for (int j = 0; j < 8; j++) {
            oacc[j][0] *= al0; oacc[j][1] *= al0;
            oacc[j][2] *= al1; oacc[j][3] *= al1;
        }
        // ---- O += P @ V ----
        #pragma unroll
        for (int ks = 0; ks < 4; ks++) {
            uint32_t pH[4] = { pk(s[2*ks][0],   s[2*ks][1]),   pk(s[2*ks][2],   s[2*ks][3]),
                               pk(s[2*ks+1][0], s[2*ks+1][1]), pk(s[2*ks+1][2], s[2*ks+1][3]) };
            uint32_t pL[4] = { pk(bres(s[2*ks][0]),   bres(s[2*ks][1])),
                               pk(bres(s[2*ks][2]),   bres(s[2*ks][3])),
                               pk(bres(s[2*ks+1][0]), bres(s[2*ks+1][1])),
                               pk(bres(s[2*ks+1][2]), bres(s[2*ks+1][3])) };
            #pragma unroll
            for (int p = 0; p < 4; p++) {
                int row = ks * 16 + ((lane >> 3) & 1) * 8 + (lane & 7);
                int c = p * 2 + (lane >> 4), ph = c ^ (row & 7);
                uint32_t vd = kb + (KVSAME ? 0u : 16384u) + row * 128 + ph * 16;
                uint32_t bvh[4], bvl[4];
                ldsm4t(bvh[0], bvh[1], bvh[2], bvh[3], vd);
                ldsm4t(bvl[0], bvl[1], bvl[2], bvl[3], vd + 8192);
                MMA(oacc[2*p],   pH, bvh);     MMA(oacc[2*p],   pH, bvl);     MMA(oacc[2*p],   pL, bvh);
                MMA(oacc[2*p+1], pH, bvh + 2); MMA(oacc[2*p+1], pH, bvl + 2); MMA(oacc[2*p+1], pL, bvh + 2);
            }
        }
        __syncthreads();
    }

    // ---- epilogue ----
    float il0 = 1.f / l0, il1 = 1.f / l1;
    const long obase = (long)zb * ozb + (long)zh * ozh;
    const long r0 = (long)(blockIdx.x * 128 + wid * 16 + (lane >> 2));
    #pragma unroll
    for (int j = 0; j < 8; j++) {
        int col = j * 8 + (lane & 3) * 2;
        float v0 = oacc[j][0] * il0, v1 = oacc[j][1] * il0;
        float v2 = oacc[j][2] * il1, v3 = oacc[j][3] * il1;
        *(uint32_t*)(Oh + obase + r0 * old_ + col)       = pk(v0, v1);
        *(uint32_t*)(Ol + obase + r0 * old_ + col)       = pk(bres(v0), bres(v1));
        *(uint32_t*)(Oh + obase + (r0 + 8) * old_ + col) = pk(v2, v3);
        *(uint32_t*)(Ol + obase + (r0 + 8) * old_ + col) = pk(bres(v2), bres(v3));
    }
}

__global__ void k_split(const float* __restrict__ in, bf16* __restrict__ oh,
                        bf16* __restrict__ ol, long n) {
    long idx = ((long)blockIdx.x * blockDim.x + threadIdx.x) * 4;
    if (idx >= n) return;
    float4 f = *(const float4*)(in + idx);
    uint2 uh; uh.x = pk(f.x, f.y); uh.y = pk(f.z, f.w);
    uint2 ul; ul.x = pk(bres(f.x), bres(f.y)); ul.y = pk(bres(f.z), bres(f.w));
    *(uint2*)(oh + idx) = uh;
    *(uint2*)(ol + idx) = ul;
}

__global__ void k_trsplit(const float* __restrict__ in, int ldin,
                          bf16* __restrict__ oh, bf16* __restrict__ ol, int ldout) {
    __shared__ float t[32][33];
    const int r0 = blockIdx.x * 32, c0 = blockIdx.y * 32;
    const int tx = threadIdx.x & 31, ty = threadIdx.x >> 5;
    #pragma unroll
    for (int i = 0; i < 4; i++) {
        int r = ty + i * 8;
        t[r][tx] = in[(long)(r0 + r) * ldin + c0 + tx];
    }
    __syncthreads();
    #pragma unroll
    for (int i = 0; i < 4; i++) {
        int oc = ty + i * 8;
        float f = t[tx][oc];
        long o = (long)(c0 + oc) * ldout + r0 + tx;
        oh[o] = __float2bfloat16(f);
        ol[o] = __float2bfloat16(bres(f));
    }
}

__global__ void gemm64(const float* __restrict__ A, const float* __restrict__ B,
                       const float* __restrict__ bias, float* __restrict__ C,
                       int Md, int Nd, int Kd) {
    __shared__ float As[16][68];
    __shared__ float Bs[16][68];
    const int tx = threadIdx.x & 15;
    const int ty = threadIdx.x >> 4;
    const int rowBase = blockIdx.y * 64;
    const int colBase = blockIdx.x * 64;
    float acc[4][4] = {};
    for (int k0 = 0; k0 < Kd; k0 += 16) {
        for (int t = threadIdx.x; t < 1024; t += 256) {
            int m = t >> 4, kk = t & 15;
            As[kk][m] = A[(long)(rowBase + m) * Kd + k0 + kk];
        }
        for (int t = threadIdx.x; t < 1024; t += 256) {
            int kk = t >> 6, n = t & 63;
            Bs[kk][n] = B[(long)(k0 + kk) * Nd + colBase + n];
        }
        __syncthreads();
        #pragma unroll
        for (int kk = 0; kk < 16; kk++) {
            float a[4], b[4];
            #pragma unroll
            for (int i = 0; i < 4; i++) a[i] = As[kk][ty * 4 + i];
            #pragma unroll
            for (int j = 0; j < 4; j++) b[j] = Bs[kk][tx * 4 + j];
            #pragma unroll
            for (int i = 0; i < 4; i++)
                #pragma unroll
                for (int j = 0; j < 4; j++) acc[i][j] += a[i] * b[j];
        }
        __syncthreads();
    }
    #pragma unroll
    for (int i = 0; i < 4; i++) {
        long r = rowBase + ty * 4 + i;
        #pragma unroll
        for (int j = 0; j < 4; j++) {
            int c = colBase + tx * 4 + j;
            float v = acc[i][j];
            if (bias) v += bias[c];
            C[r * Nd + c] = v;
        }
    }
}

__global__ void sr_conv_ln(const float* __restrict__ x, const float* __restrict__ wc,
                           const float* __restrict__ bc, const float* __restrict__ gam,
                           const float* __restrict__ bet, float* __restrict__ out) {
    const int bm = blockIdx.x;
    const int b = bm >> 10, m = bm & 1023;
    const int oi = m >> 5, oj = m & 31;
    const long base = ((long)b * NN + oi * 128 + oj * 2) * CC;
    __shared__ float red[4];
    const int tid = threadIdx.x;
    float y[4];
    float loc = 0.f;
    #pragma unroll
    for (int cc = 0; cc < 4; cc++) {
        int c = tid + cc * 128;
        float v = x[base + c]           * wc[c * 4 + 0]
                + x[base + CC + c]      * wc[c * 4 + 1]
                + x[base + 64 * CC + c] * wc[c * 4 + 2]
                + x[base + 65 * CC + c] * wc[c * 4 + 3]
                + bc[c];
        y[cc] = v; loc += v;
    }
    #pragma unroll
    for (int o = 16; o >= 1; o >>= 1) loc += __shfl_xor_sync(0xffffffffu, loc, o);
    if ((tid & 31) == 0) red[tid >> 5] = loc;
    __syncthreads();
    float mu = (red[0] + red[1] + red[2] + red[3]) * (1.f / 512.f);
    float lv = 0.f;
    #pragma unroll
    for (int cc = 0; cc < 4; cc++) { float d = y[cc] - mu; lv += d * d; }
    #pragma unroll
    for (int o = 16; o >= 1; o >>= 1) lv += __shfl_xor_sync(0xffffffffu, lv, o);
    __syncthreads();
    if ((tid & 31) == 0) red[tid >> 5] = lv;
    __syncthreads();
    float var = (red[0] + red[1] + red[2] + red[3]) * (1.f / 512.f);
    float inv = rsqrtf(var + 1e-5f);
    long ob = ((long)b * MM + m) * CC;
    #pragma unroll
    for (int cc = 0; cc < 4; cc++) {
        int c = tid + cc * 128;
        out[ob + c] = (y[cc] - mu) * inv * gam[c] + bet[c];
    }
}

extern "C" void kernel_launch(void* const* d_in, const int* in_sizes, int n_in,
                              void* d_out, int out_size) {
    const float* x         = (const float*)d_in[0];
    const float* w_qkv     = (const float*)d_in[1];
    const float* w_proj    = (const float*)d_in[2];
    const float* b_proj    = (const float*)d_in[3];
    const float* w_sr_conv = (const float*)d_in[4];
    const float* b_sr_conv = (const float*)d_in[5];
    const float* gam       = (const float*)d_in[6];
    const float* bet       = (const float*)d_in[7];
    const float* w_sr_lin  = (const float*)d_in[8];
    const float* b_sr_lin  = (const float*)d_in[9];
    float* out = (float*)d_out;

    float *xnorm, *xr;
    bf16 *qkv_h,*qkv_l,*x_h,*x_l,*wqT_h,*wqT_l,*wpT_h,*wpT_l;
    bf16 *xr_h,*xr_l,*kc_h,*kc_l,*vc_h,*vc_l,*at_h,*at_l;
    cudaGetSymbolAddress((void**)&qkv_h, g_qkv_h);
    cudaGetSymbolAddress((void**)&qkv_l, g_qkv_l);
    cudaGetSymbolAddress((void**)&x_h,   g_x_h);
    cudaGetSymbolAddress((void**)&x_l,   g_x_l);
    cudaGetSymbolAddress((void**)&wqT_h, g_wqT_h);
    cudaGetSymbolAddress((void**)&wqT_l, g_wqT_l);
    cudaGetSymbolAddress((void**)&wpT_h, g_wpT_h);
    cudaGetSymbolAddress((void**)&wpT_l, g_wpT_l);
    cudaGetSymbolAddress((void**)&xnorm, g_xnorm);
    cudaGetSymbolAddress((void**)&xr,    g_xr);
    cudaGetSymbolAddress((void**)&xr_h,  g_xr_h);
    cudaGetSymbolAddress((void**)&xr_l,  g_xr_l);
    cudaGetSymbolAddress((void**)&kc_h,  g_kc_h);
    cudaGetSymbolAddress((void**)&kc_l,  g_kc_l);
    cudaGetSymbolAddress((void**)&vc_h,  g_vc_h);
    cudaGetSymbolAddress((void**)&vc_l,  g_vc_l);
    cudaGetSymbolAddress((void**)&at_h,  g_at_h);
    cudaGetSymbolAddress((void**)&at_l,  g_at_l);

    const int SM128 = 2 * (2 * 128 * 128 + 2 * 128 * 128);  // 131072
    const int FSM_P = 64 * 1024;   // pooling: Q 32K + 2x16K stages
    const int FSM_M = 96 * 1024;   // main:    Q 32K + 2x32K stages
    cudaFuncSetAttribute((const void*)gemm_mma<128>,
                         cudaFuncAttributeMaxDynamicSharedMemorySize, SM128);
    cudaFuncSetAttribute((const void*)flash_mma<true>,
                         cudaFuncAttributeMaxDynamicSharedMemorySize, FSM_P);
    cudaFuncSetAttribute((const void*)flash_mma<false>,
                         cudaFuncAttributeMaxDynamicSharedMemorySize, FSM_M);

    const long NC3  = (long)NN * C3;
    const long KCZB = (long)HH * MM * HD;
    const long KCZH = (long)MM * HD;

    // input/weight conversions
    k_split<<<8192, 256>>>(x, x_h, x_l, (long)BB * NN * CC);
    k_trsplit<<<dim3(16, 48), 256>>>(w_qkv, C3, wqT_h, wqT_l, CC);
    k_trsplit<<<dim3(16, 16), 256>>>(w_proj, CC, wpT_h, wpT_l, CC);

    // QKV projection -> split bf16 directly
    gemm_mma<128><<<dim3(12, 128, 1), 256, SM128>>>(
        x_h, x_l, CC, 0, 0,  wqT_h, wqT_l, CC, 0, 0,
        nullptr, qkv_h, qkv_l, C3, 0, 0, nullptr, CC, 1);

    // SR branch
    sr_conv_ln<<<BB * MM, 128>>>(x, w_sr_conv, b_sr_conv, gam, bet, xnorm);
    gemm64<<<dim3(1, 64), 256>>>(xnorm, w_sr_lin, b_sr_lin, xr, BB * MM, HD, CC);
    k_split<<<256, 256>>>(xr, xr_h, xr_l, (long)BB * MM * HD);

    // merged pooling attentions: z=0 -> kc (K=k), z=1 -> vc (K=v); V aliases K
    flash_mma<true><<<dim3(8, 32, 2), 256, FSM_P>>>(
        xr_h, xr_l, HD, (long)MM * HD, 0L,
        qkv_h + CC, qkv_l + CC, C3, NC3, (long)HD, (long)CC,
        nullptr, nullptr, C3, 0L, 0L,
        kc_h, kc_l, vc_h, vc_l,
        HD, KCZB, KCZH, NN, 1.0f);

    // main attention: attn = softmax(q kc^T / 8) vc -> [b, n, h, d] split
    flash_mma<false><<<dim3(32, 32, 1), 256, FSM_M>>>(
        qkv_h, qkv_l, C3, NC3, (long)HD,
        kc_h, kc_l, HD, KCZB, KCZH, 0L,
        vc_h, vc_l, HD, KCZB, KCZH,
        at_h, at_l, nullptr, nullptr,
        CC, (long)NN * CC, (long)HD, MM, 0.125f);

    // output projection (fp32 out + bias)
    gemm_mma<128><<<dim3(4, 128, 1), 256, SM128>>>(
        at_h, at_l, CC, 0, 0, wpT_h, wpT_l, CC, 0, 0,
        out, nullptr, nullptr, CC, 0, 0, b_proj, CC, 1);
}